// round 1
// baseline (speedup 1.0000x reference)
#include <cuda_runtime.h>
#include <cuda_bf16.h>
#include <mma.h>

using namespace nvcuda;

// ---------------- problem constants ----------------
#define BATCH   8
#define SEQ     2048
#define DMODEL  256
#define NHEAD   8
#define DHEAD   32
#define NHID    1024
#define NLAY    4
#define NTOK    (BATCH*SEQ)        // 16384
#define LOUT    50
#define ATT_SCALE 0.17677669529663687f   // 1/sqrt(32)

// ---------------- scratch (device globals; no cudaMalloc allowed) ----------------
__device__ __align__(256) float          d_X32 [NTOK*DMODEL];
__device__ __align__(256) __nv_bfloat16  d_Xb  [NTOK*DMODEL];
__device__ __align__(256) __nv_bfloat16  d_QKVb[NTOK*3*DMODEL];
__device__ __align__(256) __nv_bfloat16  d_ATTb[NTOK*DMODEL];
__device__ __align__(256) float          d_TMP [NTOK*DMODEL];
__device__ __align__(256) __nv_bfloat16  d_Hb  [NTOK*NHID];
__device__ __align__(256) __nv_bfloat16  d_WqkvB[NLAY*3*DMODEL*DMODEL];
__device__ __align__(256) __nv_bfloat16  d_WoB  [NLAY*DMODEL*DMODEL];
__device__ __align__(256) __nv_bfloat16  d_W1B  [NLAY*NHID*DMODEL];
__device__ __align__(256) __nv_bfloat16  d_W2B  [NLAY*DMODEL*NHID];

// ---------------- fp32 -> bf16 weight conversion ----------------
__global__ void conv_kernel(const float* __restrict__ src, __nv_bfloat16* __restrict__ dst, int n)
{
    for (int i = blockIdx.x*blockDim.x + threadIdx.x; i < n; i += gridDim.x*blockDim.x)
        dst[i] = __float2bfloat16(src[i]);
}

// ---------------- embedding: x = y * W_emb + b_emb ----------------
__global__ void embed_kernel(const float* __restrict__ inputs,
                             const float* __restrict__ W_emb,
                             const float* __restrict__ b_emb)
{
    int tok = blockIdx.x;
    int d   = threadIdx.x;
    float y = inputs[(size_t)tok*4];
    float v = y * W_emb[d] + b_emb[d];
    size_t gi = (size_t)tok*DMODEL + d;
    d_X32[gi] = v;
    d_Xb[gi]  = __float2bfloat16(v);
}

// ---------------- generic bf16 TN GEMM: C = A(MxK) * B(NxK)^T + bias [+resid][relu] ----------------
// block tile 128x64, BK=32, 8 warps (4x2), each warp 32x32 (2x2 wmma 16x16x16)
__global__ __launch_bounds__(256) void gemm_kernel(
    const __nv_bfloat16* __restrict__ A,
    const __nv_bfloat16* __restrict__ B,
    const float* __restrict__ bias,
    const float* __restrict__ resid,      // nullable, fp32 (M,N)
    float* __restrict__ outF,             // nullable
    __nv_bfloat16* __restrict__ outB,     // nullable
    int N, int K, int relu, int mStride, int mOff)
{
    __shared__ __align__(128) float Cs[128*68];                 // 34816B; aliased for A/B tiles
    __nv_bfloat16* As = reinterpret_cast<__nv_bfloat16*>(Cs);   // 128*40 bf16
    __nv_bfloat16* Bs = As + 128*40;                            // 64*40 bf16

    int tid = threadIdx.x;
    int wid = tid >> 5;
    int wm  = wid >> 1, wn = wid & 1;
    int m0  = (blockIdx.y * mStride + mOff) * 128;
    int n0  = blockIdx.x * 64;

    wmma::fragment<wmma::accumulator,16,16,16,float> cf[2][2];
    #pragma unroll
    for (int i=0;i<2;i++)
        #pragma unroll
        for (int j=0;j<2;j++) wmma::fill_fragment(cf[i][j], 0.f);

    for (int k0 = 0; k0 < K; k0 += 32) {
        #pragma unroll
        for (int i=0;i<4;i++){
            int r = (tid>>3) + i*32;
            int c = (tid&7)*4;
            *(uint2*)&As[r*40+c] = *(const uint2*)&A[(size_t)(m0+r)*K + k0 + c];
        }
        #pragma unroll
        for (int i=0;i<2;i++){
            int r = (tid>>3) + i*32;
            int c = (tid&7)*4;
            *(uint2*)&Bs[r*40+c] = *(const uint2*)&B[(size_t)(n0+r)*K + k0 + c];
        }
        __syncthreads();
        #pragma unroll
        for (int kk=0; kk<32; kk+=16){
            wmma::fragment<wmma::matrix_a,16,16,16,__nv_bfloat16,wmma::row_major> af[2];
            wmma::fragment<wmma::matrix_b,16,16,16,__nv_bfloat16,wmma::col_major> bfr[2];
            #pragma unroll
            for (int i=0;i<2;i++) wmma::load_matrix_sync(af[i],  &As[(wm*32+i*16)*40+kk], 40);
            #pragma unroll
            for (int j=0;j<2;j++) wmma::load_matrix_sync(bfr[j], &Bs[(wn*32+j*16)*40+kk], 40);
            #pragma unroll
            for (int i=0;i<2;i++)
                #pragma unroll
                for (int j=0;j<2;j++)
                    wmma::mma_sync(cf[i][j], af[i], bfr[j], cf[i][j]);
        }
        __syncthreads();
    }
    #pragma unroll
    for (int i=0;i<2;i++)
        #pragma unroll
        for (int j=0;j<2;j++)
            wmma::store_matrix_sync(&Cs[(wm*32+i*16)*68 + wn*32 + j*16], cf[i][j], 68, wmma::mem_row_major);
    __syncthreads();
    for (int e = tid; e < 128*64; e += 256){
        int cm = e >> 6, cn = e & 63;
        float v = Cs[cm*68+cn] + bias[n0+cn];
        if (relu) v = fmaxf(v, 0.f);
        size_t gi = (size_t)(m0+cm)*N + n0 + cn;
        if (resid) v += resid[gi];
        if (outF)  outF[gi] = v;
        if (outB)  outB[gi] = __float2bfloat16(v);
    }
}

// ---------------- flash attention (causal), 64-row q tile, DH=32, 4 warps ----------------
__global__ __launch_bounds__(128) void attn_kernel(int qtOffset)
{
    __shared__ __align__(128) __nv_bfloat16 Qs[64*32];
    __shared__ __align__(128) __nv_bfloat16 Ks[64*32];
    __shared__ __align__(128) __nv_bfloat16 Vs[64*32];
    __shared__ __align__(128) float         Sf[64*64];
    __shared__ __align__(128) __nv_bfloat16 Pb[64*64];
    __shared__ __align__(128) float         Of[64*32];
    __shared__ float mrow[64], lrow[64];

    int tid = threadIdx.x;
    int wid = tid >> 5;
    int qt  = blockIdx.x + qtOffset;
    int bh  = blockIdx.y;
    int b   = bh >> 3, h = bh & 7;

    const __nv_bfloat16* Qg = d_QKVb + ((size_t)(b*SEQ + qt*64))*768 + h*32;
    #pragma unroll
    for (int i=0;i<4;i++){
        int r = (tid>>3) + i*16;
        int c = (tid&7)*4;
        *(uint2*)&Qs[r*32+c] = *(const uint2*)&Qg[(size_t)r*768 + c];
    }
    for (int e=tid; e<64*32; e+=128) Of[e] = 0.f;
    if (tid < 64){ mrow[tid] = -1e30f; lrow[tid] = 0.f; }
    __syncthreads();

    for (int kt = 0; kt <= qt; kt++){
        const __nv_bfloat16* Kg = d_QKVb + ((size_t)(b*SEQ + kt*64))*768 + 256 + h*32;
        const __nv_bfloat16* Vg = Kg + 256;
        #pragma unroll
        for (int i=0;i<4;i++){
            int r = (tid>>3) + i*16, c = (tid&7)*4;
            *(uint2*)&Ks[r*32+c] = *(const uint2*)&Kg[(size_t)r*768 + c];
            *(uint2*)&Vs[r*32+c] = *(const uint2*)&Vg[(size_t)r*768 + c];
        }
        __syncthreads();

        // S = Q K^T : 64x64, warps 2x2 each 32x32
        {
            int wm = wid >> 1, wn = wid & 1;
            wmma::fragment<wmma::accumulator,16,16,16,float> sc[2][2];
            #pragma unroll
            for (int i=0;i<2;i++)
                #pragma unroll
                for (int j=0;j<2;j++) wmma::fill_fragment(sc[i][j], 0.f);
            #pragma unroll
            for (int kk=0; kk<32; kk+=16){
                wmma::fragment<wmma::matrix_a,16,16,16,__nv_bfloat16,wmma::row_major> af[2];
                wmma::fragment<wmma::matrix_b,16,16,16,__nv_bfloat16,wmma::col_major> bfr[2];
                #pragma unroll
                for (int i=0;i<2;i++) wmma::load_matrix_sync(af[i],  &Qs[(wm*32+i*16)*32+kk], 32);
                #pragma unroll
                for (int j=0;j<2;j++) wmma::load_matrix_sync(bfr[j], &Ks[(wn*32+j*16)*32+kk], 32);
                #pragma unroll
                for (int i=0;i<2;i++)
                    #pragma unroll
                    for (int j=0;j<2;j++)
                        wmma::mma_sync(sc[i][j], af[i], bfr[j], sc[i][j]);
            }
            #pragma unroll
            for (int i=0;i<2;i++)
                #pragma unroll
                for (int j=0;j<2;j++)
                    wmma::store_matrix_sync(&Sf[(wm*32+i*16)*64 + wn*32 + j*16], sc[i][j], 64, wmma::mem_row_major);
        }
        __syncthreads();

        // online softmax: 2 threads per row
        {
            int r = tid >> 1, halfsel = tid & 1;
            int grow = qt*64 + r;
            int cb = halfsel*32;
            float mloc = -1e30f;
            for (int c=0;c<32;c++){
                int gc = kt*64 + cb + c;
                float v = Sf[r*64+cb+c] * ATT_SCALE;
                v = (gc <= grow) ? v : -1e30f;
                Sf[r*64+cb+c] = v;
                mloc = fmaxf(mloc, v);
            }
            mloc = fmaxf(mloc, __shfl_xor_sync(0xffffffffu, mloc, 1));
            float mold = mrow[r];
            float newm = fmaxf(mold, mloc);
            float corr = __expf(mold - newm);
            float ssum = 0.f;
            for (int c=0;c<32;c++){
                float e = __expf(Sf[r*64+cb+c] - newm);
                Pb[r*64+cb+c] = __float2bfloat16(e);
                ssum += e;
            }
            ssum += __shfl_xor_sync(0xffffffffu, ssum, 1);
            if (!halfsel){ lrow[r] = lrow[r]*corr + ssum; mrow[r] = newm; }
            #pragma unroll
            for (int c=0;c<16;c++) Of[r*32 + halfsel*16 + c] *= corr;
        }
        __syncthreads();

        // O += P V : 64x32, warps 2x2 each 32x16
        {
            int wm = wid >> 1, wn = wid & 1;
            wmma::fragment<wmma::accumulator,16,16,16,float> oc[2];
            #pragma unroll
            for (int i=0;i<2;i++)
                wmma::load_matrix_sync(oc[i], &Of[(wm*32+i*16)*32 + wn*16], 32, wmma::mem_row_major);
            #pragma unroll
            for (int kk=0; kk<64; kk+=16){
                wmma::fragment<wmma::matrix_b,16,16,16,__nv_bfloat16,wmma::row_major> vb;
                wmma::load_matrix_sync(vb, &Vs[kk*32 + wn*16], 32);
                #pragma unroll
                for (int i=0;i<2;i++){
                    wmma::fragment<wmma::matrix_a,16,16,16,__nv_bfloat16,wmma::row_major> pa;
                    wmma::load_matrix_sync(pa, &Pb[(wm*32+i*16)*64 + kk], 64);
                    wmma::mma_sync(oc[i], pa, vb, oc[i]);
                }
            }
            #pragma unroll
            for (int i=0;i<2;i++)
                wmma::store_matrix_sync(&Of[(wm*32+i*16)*32 + wn*16], oc[i], 32, wmma::mem_row_major);
        }
        __syncthreads();
    }

    __nv_bfloat16* Og = d_ATTb + ((size_t)(b*SEQ + qt*64))*256 + h*32;
    for (int e = tid; e < 64*32; e += 128){
        int r = e >> 5, d = e & 31;
        float o = Of[e] / lrow[r];
        Og[(size_t)r*256 + d] = __float2bfloat16(o);
    }
}

// ---------------- layernorm: warp per token, writes fp32 + bf16 ----------------
__global__ __launch_bounds__(256) void ln_kernel(const float* __restrict__ in,
    const float* __restrict__ g, const float* __restrict__ bta, int sparse)
{
    int raw  = blockIdx.x*8 + (threadIdx.x>>5);
    int tok  = sparse ? ((raw>>7)*SEQ + 1920 + (raw&127)) : raw;
    int lane = threadIdx.x & 31;
    const float* row = in + (size_t)tok*DMODEL;
    float v[8]; float s = 0.f;
    #pragma unroll
    for (int i=0;i<8;i++){ v[i] = row[lane + i*32]; s += v[i]; }
    #pragma unroll
    for (int o=16;o>0;o>>=1) s += __shfl_xor_sync(0xffffffffu, s, o);
    float mean = s * (1.f/256.f);
    float q = 0.f;
    #pragma unroll
    for (int i=0;i<8;i++){ float d = v[i]-mean; q += d*d; }
    #pragma unroll
    for (int o=16;o>0;o>>=1) q += __shfl_xor_sync(0xffffffffu, q, o);
    float rstd = rsqrtf(q*(1.f/256.f) + 1e-5f);
    #pragma unroll
    for (int i=0;i<8;i++){
        int d_ = lane + i*32;
        float o = (v[i]-mean)*rstd*g[d_] + bta[d_];
        size_t gi = (size_t)tok*DMODEL + d_;
        d_X32[gi] = o;
        d_Xb[gi]  = __float2bfloat16(o);
    }
}

// ---------------- dec + hist + IDM + fusion (one block) ----------------
__global__ void final_kernel(const float* __restrict__ inputs,
    const float* __restrict__ his,
    const float* __restrict__ W_dec, const float* __restrict__ b_dec,
    const float* __restrict__ W_fus, const float* __restrict__ b_fus,
    float* __restrict__ out)
{
    __shared__ float dec[8], yidm[8][LOUT], lastpos[8], dvb[8];
    int tid = threadIdx.x, wid = tid>>5, lane = tid&31;

    // dec[b] = X32[last_tok(b)] . W_dec + b_dec  (warp per batch)
    {
        const float* row = d_X32 + ((size_t)(wid*SEQ + SEQ-1))*DMODEL;
        float s = 0.f;
        #pragma unroll
        for (int i=0;i<8;i++){ int d_ = lane + i*32; s += row[d_]*W_dec[d_]; }
        #pragma unroll
        for (int o=16;o>0;o>>=1) s += __shfl_xor_sync(0xffffffffu, s, o);
        if (lane==0) dec[wid] = s + b_dec[0];
    }
    if (tid < 8){
        int b = tid;
        float lp = inputs[((size_t)(b*SEQ + SEQ-1))*4];
        lastpos[b] = lp;
        dvb[b] = (lp - inputs[((size_t)(b*SEQ + SEQ-1-LOUT))*4]) / 50.f;
    }
    __syncthreads();

    // IDM (exactly mirrors reference, including v0[-1] broadcast quirk)
    if (tid < 8){
        int b = tid;
        const float* il = inputs + ((size_t)(b*SEQ + SEQ-1))*4;
        float y = il[0], v = il[1], sg = il[2], dv = il[3];
        const float sqab2 = 2.449489742783178f;   // 2*sqrt(1.0*1.5)
        float sx = 2.0f + fmaxf(0.f, v*1.5f + v*dv/sqab2);
        float t = v/30.0f; float p = t*t; p *= p;
        float rr = sx/sg;
        float af = (1.f - p - rr*rr);             // A_IDM = 1.0
        float v0 = fmaxf(v + af*0.1f, 0.f);
        float v0last = __shfl_sync(0xffu, v0, 7); // reference bug: v0[-1] for all b
        float yp = y + v0last*0.1f;
        float vp = v0;
        yidm[b][0] = yp;
        for (int j=0;j<LOUT-1;j++){
            float hp = his[((size_t)(b*LOUT + j))*2];
            float hv = his[((size_t)(b*LOUT + j))*2 + 1];
            float dvj = hv - vp;
            float sj  = hp - yp;
            float sxj = 2.0f + fmaxf(0.f, vp*1.5f + vp*dvj/sqab2);
            float tt = vp/30.0f; float q4 = tt*tt; q4 *= q4;
            float r2 = sxj/sj;
            float acc = (1.f - q4 - r2*r2);
            float v2 = vp + acc*0.1f;
            v2 = (v2 <= 0.f) ? 0.f : v2;
            yp = yp + v2*0.1f;
            yidm[b][j+1] = yp;
            vp = v2;
        }
    }
    __syncthreads();

    float w0 = W_fus[0], w1 = W_fus[1], w2 = W_fus[2], bb = b_fus[0];
    for (int t = tid; t < BATCH*LOUT; t += 256){
        int b = t / LOUT, l = t % LOUT;
        out[t] = w0*dec[b] + w1*(lastpos[b] + dvb[b]*(float)(l+1)) + w2*yidm[b][l] + bb;
    }
}

// ---------------- launcher ----------------
extern "C" void kernel_launch(void* const* d_in, const int* in_sizes, int n_in,
                              void* d_out, int out_size)
{
    (void)in_sizes; (void)n_in; (void)out_size;
    const float* inputs = (const float*)d_in[0];
    const float* his    = (const float*)d_in[1];
    const float* W_emb  = (const float*)d_in[2];
    const float* b_emb  = (const float*)d_in[3];
    const float* Wqkv   = (const float*)d_in[4];
    const float* bqkv   = (const float*)d_in[5];
    const float* Wo     = (const float*)d_in[6];
    const float* bo     = (const float*)d_in[7];
    const float* W1     = (const float*)d_in[8];
    const float* b1     = (const float*)d_in[9];
    const float* W2     = (const float*)d_in[10];
    const float* b2     = (const float*)d_in[11];
    const float* ln1g   = (const float*)d_in[12];
    const float* ln1b   = (const float*)d_in[13];
    const float* ln2g   = (const float*)d_in[14];
    const float* ln2b   = (const float*)d_in[15];
    const float* W_dec  = (const float*)d_in[16];
    const float* b_dec  = (const float*)d_in[17];
    const float* W_fus  = (const float*)d_in[18];
    const float* b_fus  = (const float*)d_in[19];
    float* out = (float*)d_out;

    void *pXb_, *pQKV_, *pATT_, *pTMP_, *pHb_, *pWq_, *pWo_, *pW1_, *pW2_;
    cudaGetSymbolAddress(&pXb_,  d_Xb);
    cudaGetSymbolAddress(&pQKV_, d_QKVb);
    cudaGetSymbolAddress(&pATT_, d_ATTb);
    cudaGetSymbolAddress(&pTMP_, d_TMP);
    cudaGetSymbolAddress(&pHb_,  d_Hb);
    cudaGetSymbolAddress(&pWq_,  d_WqkvB);
    cudaGetSymbolAddress(&pWo_,  d_WoB);
    cudaGetSymbolAddress(&pW1_,  d_W1B);
    cudaGetSymbolAddress(&pW2_,  d_W2B);
    void *pX32_;
    cudaGetSymbolAddress(&pX32_, d_X32);

    __nv_bfloat16* Xb   = (__nv_bfloat16*)pXb_;
    __nv_bfloat16* QKVb = (__nv_bfloat16*)pQKV_;
    __nv_bfloat16* ATTb = (__nv_bfloat16*)pATT_;
    float*         TMP  = (float*)pTMP_;
    float*         X32  = (float*)pX32_;
    __nv_bfloat16* Hb   = (__nv_bfloat16*)pHb_;
    __nv_bfloat16* WqB  = (__nv_bfloat16*)pWq_;
    __nv_bfloat16* WoB  = (__nv_bfloat16*)pWo_;
    __nv_bfloat16* W1B  = (__nv_bfloat16*)pW1_;
    __nv_bfloat16* W2B  = (__nv_bfloat16*)pW2_;

    // weights -> bf16
    conv_kernel<<<(NLAY*768*256+255)/256, 256>>>(Wqkv, WqB, NLAY*768*256);
    conv_kernel<<<(NLAY*256*256+255)/256, 256>>>(Wo,   WoB, NLAY*256*256);
    conv_kernel<<<(NLAY*1024*256+255)/256,256>>>(W1,   W1B, NLAY*1024*256);
    conv_kernel<<<(NLAY*256*1024+255)/256,256>>>(W2,   W2B, NLAY*256*1024);

    embed_kernel<<<NTOK, 256>>>(inputs, W_emb, b_emb);

    for (int l = 0; l < NLAY; l++){
        int sp      = (l == NLAY-1);
        int gridY   = sp ? 8  : 128;
        int mStride = sp ? 16 : 1;
        int mOff    = sp ? 15 : 0;

        // QKV (full M always: K,V needed for all tokens)
        gemm_kernel<<<dim3(12,128), 256>>>(Xb, WqB + (size_t)l*768*256,
            bqkv + l*768, nullptr, nullptr, QKVb, 768, 256, 0, 1, 0);

        // attention
        if (!sp) attn_kernel<<<dim3(32,64), 128>>>(0);
        else     attn_kernel<<<dim3(1,64),  128>>>(31);

        // Wo + residual -> TMP (fp32)
        gemm_kernel<<<dim3(4,gridY), 256>>>(ATTb, WoB + (size_t)l*256*256,
            bo + l*256, X32, TMP, nullptr, 256, 256, 0, mStride, mOff);

        ln_kernel<<<sp?128:2048, 256>>>(TMP, ln1g + l*256, ln1b + l*256, sp);

        // FFN1 relu -> Hb (bf16)
        gemm_kernel<<<dim3(16,gridY), 256>>>(Xb, W1B + (size_t)l*1024*256,
            b1 + l*1024, nullptr, nullptr, Hb, 1024, 256, 1, mStride, mOff);

        // FFN2 + residual -> TMP
        gemm_kernel<<<dim3(4,gridY), 256>>>(Hb, W2B + (size_t)l*256*1024,
            b2 + l*256, X32, TMP, nullptr, 256, 1024, 0, mStride, mOff);

        ln_kernel<<<sp?128:2048, 256>>>(TMP, ln2g + l*256, ln2b + l*256, sp);
    }

    final_kernel<<<1, 256>>>(inputs, his, W_dec, b_dec, W_fus, b_fus, out);
}

// round 2
// speedup vs baseline: 3.4649x; 3.4649x over previous
#include <cuda_runtime.h>
#include <cuda_bf16.h>
#include <mma.h>

using namespace nvcuda;

// ---------------- problem constants ----------------
#define BATCH   8
#define SEQ     2048
#define DMODEL  256
#define NHEAD   8
#define DHEAD   32
#define NHID    1024
#define NLAY    4
#define NTOK    (BATCH*SEQ)        // 16384
#define LOUT    50
#define ATT_SCALE 0.17677669529663687f   // 1/sqrt(32)

// ---------------- scratch ----------------
__device__ __align__(256) float          d_X32 [NTOK*DMODEL];
__device__ __align__(256) __nv_bfloat16  d_Xb  [NTOK*DMODEL];
__device__ __align__(256) __nv_bfloat16  d_QKVb[NTOK*3*DMODEL];
__device__ __align__(256) __nv_bfloat16  d_ATTb[NTOK*DMODEL];
__device__ __align__(256) float          d_TMP [NTOK*DMODEL];
__device__ __align__(256) __nv_bfloat16  d_Hb  [NTOK*NHID];
__device__ __align__(256) __nv_bfloat16  d_WqkvB[NLAY*3*DMODEL*DMODEL];
__device__ __align__(256) __nv_bfloat16  d_WoB  [NLAY*DMODEL*DMODEL];
__device__ __align__(256) __nv_bfloat16  d_W1B  [NLAY*NHID*DMODEL];
__device__ __align__(256) __nv_bfloat16  d_W2B  [NLAY*DMODEL*NHID];

// ---------------- PTX helpers ----------------
__device__ __forceinline__ unsigned smem_u32(const void* p){
    return (unsigned)__cvta_generic_to_shared(p);
}
#define CPA(dst, src) asm volatile("cp.async.cg.shared.global [%0], [%1], 16;" :: "r"(dst), "l"(src))
#define CPC() asm volatile("cp.async.commit_group;")
#define CPW0() asm volatile("cp.async.wait_group 0;")
#define CPW1() asm volatile("cp.async.wait_group 1;")
#define LDSM4(r0,r1,r2,r3,a) asm volatile("ldmatrix.sync.aligned.m8n8.x4.shared.b16 {%0,%1,%2,%3}, [%4];" \
    : "=r"(r0),"=r"(r1),"=r"(r2),"=r"(r3) : "r"(a))
#define LDSM4T(r0,r1,r2,r3,a) asm volatile("ldmatrix.sync.aligned.m8n8.x4.trans.shared.b16 {%0,%1,%2,%3}, [%4];" \
    : "=r"(r0),"=r"(r1),"=r"(r2),"=r"(r3) : "r"(a))
#define MMA16816(d0,d1,d2,d3, a0,a1,a2,a3, b0,b1) \
    asm volatile("mma.sync.aligned.m16n8k16.row.col.f32.bf16.bf16.f32 " \
        "{%0,%1,%2,%3}, {%4,%5,%6,%7}, {%8,%9}, {%0,%1,%2,%3};" \
        : "+f"(d0),"+f"(d1),"+f"(d2),"+f"(d3) \
        : "r"(a0),"r"(a1),"r"(a2),"r"(a3), "r"(b0),"r"(b1))

__device__ __forceinline__ unsigned pkbf2(float lo, float hi){
    unsigned d;
    asm("cvt.rn.bf16x2.f32 %0, %1, %2;" : "=r"(d) : "f"(hi), "f"(lo));
    return d;
}
// Schraudolph fast exp of SA*(s - m) given base = B0 - SA*m; clamped so masked (-1e30) -> 0
#define EXP_B0 1064986316.0f
__device__ __forceinline__ float cexp(float s, float SA, float base){
    float t = fmaf(s, SA, base);
    t = fmaxf(t, 0.f);
    return __int_as_float((int)t);
}

// ---------------- fp32 -> bf16 weight conversion ----------------
__global__ void conv_kernel(const float* __restrict__ src, __nv_bfloat16* __restrict__ dst, int n)
{
    for (int i = blockIdx.x*blockDim.x + threadIdx.x; i < n; i += gridDim.x*blockDim.x)
        dst[i] = __float2bfloat16(src[i]);
}

// ---------------- embedding ----------------
__global__ void embed_kernel(const float* __restrict__ inputs,
                             const float* __restrict__ W_emb,
                             const float* __restrict__ b_emb)
{
    int tok = blockIdx.x;
    int d   = threadIdx.x;
    float y = inputs[(size_t)tok*4];
    float v = y * W_emb[d] + b_emb[d];
    size_t gi = (size_t)tok*DMODEL + d;
    d_X32[gi] = v;
    d_Xb[gi]  = __float2bfloat16(v);
}

// ---------------- GEMM: C = A(MxK) * B(NxK)^T + bias [+resid][relu] ----------------
// tile 128x128, BK=32, cp.async double buffered, 8 warps 4x2 each 32x64
__global__ __launch_bounds__(256) void gemm_kernel(
    const __nv_bfloat16* __restrict__ A,
    const __nv_bfloat16* __restrict__ B,
    const float* __restrict__ bias,
    const float* __restrict__ resid,
    float* __restrict__ outF,
    __nv_bfloat16* __restrict__ outB,
    int N, int K, int relu, int mStride, int mOff)
{
    __shared__ __align__(16) unsigned char sm_raw[41088];
    __nv_bfloat16* As = (__nv_bfloat16*)sm_raw;      // [2][128*40]
    __nv_bfloat16* Bs = As + 2*128*40;               // [2][128*40]
    float*         Cs = (float*)sm_raw;              // 64*136

    const int tid = threadIdx.x;
    const int wid = tid >> 5;
    const int wm  = wid >> 1, wn = wid & 1;
    const int m0  = (blockIdx.y * mStride + mOff) * 128;
    const int n0  = blockIdx.x * 128;

    wmma::fragment<wmma::accumulator,16,16,16,float> cf[2][4];
    #pragma unroll
    for (int i=0;i<2;i++)
        #pragma unroll
        for (int j=0;j<4;j++) wmma::fill_fragment(cf[i][j], 0.f);

    const int kIter = K >> 5;

    // issue loads for k-step i into buffer bf
    auto issue = [&](int i, int bf){
        const __nv_bfloat16* Ag = A + (size_t)m0*K + i*32;
        const __nv_bfloat16* Bg = B + (size_t)n0*K + i*32;
        __nv_bfloat16* Ad = As + bf*5120;
        __nv_bfloat16* Bd = Bs + bf*5120;
        #pragma unroll
        for (int c = tid; c < 512; c += 256){
            int r = c >> 2, off = (c & 3)*8;
            CPA(smem_u32(&Ad[r*40+off]), Ag + (size_t)r*K + off);
            CPA(smem_u32(&Bd[r*40+off]), Bg + (size_t)r*K + off);
        }
    };

    issue(0, 0); CPC();
    for (int i = 0; i < kIter; i++){
        int buf = i & 1;
        if (i+1 < kIter){ issue(i+1, (i+1)&1); CPC(); CPW1(); }
        else            { CPW0(); }
        __syncthreads();
        const __nv_bfloat16* Asb = As + buf*5120;
        const __nv_bfloat16* Bsb = Bs + buf*5120;
        #pragma unroll
        for (int kk = 0; kk < 32; kk += 16){
            wmma::fragment<wmma::matrix_a,16,16,16,__nv_bfloat16,wmma::row_major> af[2];
            wmma::fragment<wmma::matrix_b,16,16,16,__nv_bfloat16,wmma::col_major> bfr[4];
            #pragma unroll
            for (int x=0;x<2;x++) wmma::load_matrix_sync(af[x],  &Asb[(wm*32 + x*16)*40 + kk], 40);
            #pragma unroll
            for (int j=0;j<4;j++) wmma::load_matrix_sync(bfr[j], &Bsb[(wn*64 + j*16)*40 + kk], 40);
            #pragma unroll
            for (int x=0;x<2;x++)
                #pragma unroll
                for (int j=0;j<4;j++)
                    wmma::mma_sync(cf[x][j], af[x], bfr[j], cf[x][j]);
        }
        __syncthreads();
    }

    // epilogue: 2 chunks of 64 rows through reused smem
    #pragma unroll
    for (int chunk = 0; chunk < 2; chunk++){
        if ((wm >> 1) == chunk){
            #pragma unroll
            for (int x=0;x<2;x++)
                #pragma unroll
                for (int j=0;j<4;j++)
                    wmma::store_matrix_sync(&Cs[((wm&1)*32 + x*16)*136 + wn*64 + j*16],
                                            cf[x][j], 136, wmma::mem_row_major);
        }
        __syncthreads();
        for (int e = tid; e < 64*128; e += 256){
            int cm = e >> 7, cn = e & 127;
            float v = Cs[cm*136+cn] + bias[n0+cn];
            if (relu) v = fmaxf(v, 0.f);
            size_t gi = (size_t)(m0 + chunk*64 + cm)*N + n0 + cn;
            if (resid) v += resid[gi];
            if (outF)  outF[gi] = v;
            if (outB)  outB[gi] = __float2bfloat16(v);
        }
        __syncthreads();
    }
}

// ---------------- flash attention: register-resident, raw mma, fast exp ----------------
// block 128 threads (4 warps), q-tile 64 (warp w owns rows w*16..+15), kt tile 64, DH=32
__global__ __launch_bounds__(128) void attn_kernel(int qtOffset)
{
    __shared__ __align__(16) __nv_bfloat16 Qs[64*40];
    __shared__ __align__(16) __nv_bfloat16 Ks[2][64*40];
    __shared__ __align__(16) __nv_bfloat16 Vs[2][64*40];

    const int tid = threadIdx.x, lane = tid & 31, w = tid >> 5;
    const int qt = blockIdx.x + qtOffset;
    const int bh = blockIdx.y, b = bh >> 3, h = bh & 7;
    const int g = lane >> 2, tig = lane & 3;
    const int r8 = lane & 7, sel = lane >> 3;
    const float SA = 12102203.161f * ATT_SCALE;

    // load Q tile (64x32) into smem
    const __nv_bfloat16* Qg = d_QKVb + ((size_t)(b*SEQ + qt*64))*768 + h*32;
    #pragma unroll
    for (int c = tid; c < 256; c += 128){
        int r = c >> 2, off = (c & 3)*8;
        *(uint4*)&Qs[r*40+off] = *(const uint4*)&Qg[(size_t)r*768 + off];
    }

    // prologue K/V load for kt=0
    {
        const __nv_bfloat16* Kg = d_QKVb + ((size_t)(b*SEQ))*768 + 256 + h*32;
        const __nv_bfloat16* Vg = Kg + 256;
        #pragma unroll
        for (int c = tid; c < 256; c += 128){
            int r = c >> 2, off = (c & 3)*8;
            CPA(smem_u32(&Ks[0][r*40+off]), Kg + (size_t)r*768 + off);
            CPA(smem_u32(&Vs[0][r*40+off]), Vg + (size_t)r*768 + off);
        }
        CPC();
    }
    __syncthreads();

    // Q fragments (A of m16n8k16), two k16 steps
    unsigned aq[2][4];
    {
        int row = w*16 + (sel & 1)*8 + r8;
        #pragma unroll
        for (int t=0;t<2;t++){
            unsigned addr = smem_u32(&Qs[row*40 + t*16 + (sel>>1)*8]);
            LDSM4(aq[t][0], aq[t][1], aq[t][2], aq[t][3], addr);
        }
    }

    float o[4][4];
    #pragma unroll
    for (int j=0;j<4;j++){ o[j][0]=0.f;o[j][1]=0.f;o[j][2]=0.f;o[j][3]=0.f; }
    float m0v = -1e30f, m1v = -1e30f, l0 = 0.f, l1 = 0.f;
    const int rowg = w*16 + g;

    for (int kt = 0; kt <= qt; kt++){
        int buf = kt & 1;
        if (kt < qt){
            int nb = (kt+1) & 1;
            const __nv_bfloat16* Kg = d_QKVb + ((size_t)(b*SEQ + (kt+1)*64))*768 + 256 + h*32;
            const __nv_bfloat16* Vg = Kg + 256;
            #pragma unroll
            for (int c = tid; c < 256; c += 128){
                int r = c >> 2, off = (c & 3)*8;
                CPA(smem_u32(&Ks[nb][r*40+off]), Kg + (size_t)r*768 + off);
                CPA(smem_u32(&Vs[nb][r*40+off]), Vg + (size_t)r*768 + off);
            }
            CPC(); CPW1();
        } else {
            CPW0();
        }
        __syncthreads();

        const __nv_bfloat16* Kb = Ks[buf];
        const __nv_bfloat16* Vb = Vs[buf];

        // S = Q K^T : 8 n-tiles of 8 cols
        float s[8][4];
        #pragma unroll
        for (int j=0;j<8;j++){
            s[j][0]=0.f;s[j][1]=0.f;s[j][2]=0.f;s[j][3]=0.f;
            unsigned k0,k1,k2,k3;
            unsigned addr = smem_u32(&Kb[(j*8 + r8)*40 + sel*8]);
            LDSM4(k0,k1,k2,k3, addr);
            MMA16816(s[j][0],s[j][1],s[j][2],s[j][3],
                     aq[0][0],aq[0][1],aq[0][2],aq[0][3], k0,k1);
            MMA16816(s[j][0],s[j][1],s[j][2],s[j][3],
                     aq[1][0],aq[1][1],aq[1][2],aq[1][3], k2,k3);
        }

        if (kt == qt){
            #pragma unroll
            for (int j=0;j<8;j++){
                int c0 = j*8 + 2*tig;
                if (c0   > rowg)   s[j][0] = -1e30f;
                if (c0+1 > rowg)   s[j][1] = -1e30f;
                if (c0   > rowg+8) s[j][2] = -1e30f;
                if (c0+1 > rowg+8) s[j][3] = -1e30f;
            }
        }

        // row max (rows g, g+8), across quad
        float mt0 = -1e30f, mt1 = -1e30f;
        #pragma unroll
        for (int j=0;j<8;j++){
            mt0 = fmaxf(mt0, fmaxf(s[j][0], s[j][1]));
            mt1 = fmaxf(mt1, fmaxf(s[j][2], s[j][3]));
        }
        mt0 = fmaxf(mt0, __shfl_xor_sync(0xffffffffu, mt0, 1));
        mt0 = fmaxf(mt0, __shfl_xor_sync(0xffffffffu, mt0, 2));
        mt1 = fmaxf(mt1, __shfl_xor_sync(0xffffffffu, mt1, 1));
        mt1 = fmaxf(mt1, __shfl_xor_sync(0xffffffffu, mt1, 2));
        float nm0 = fmaxf(m0v, mt0), nm1 = fmaxf(m1v, mt1);
        float base0 = EXP_B0 - SA*nm0, base1 = EXP_B0 - SA*nm1;
        float corr0 = cexp(m0v, SA, base0), corr1 = cexp(m1v, SA, base1);
        m0v = nm0; m1v = nm1;

        // exp + pack P as A fragments (4 k16 tiles over kt)
        float rs0 = 0.f, rs1 = 0.f;
        unsigned pp[4][4];
        #pragma unroll
        for (int t=0;t<4;t++){
            float p00 = cexp(s[2*t][0],  SA, base0), p01 = cexp(s[2*t][1],  SA, base0);
            float p02 = cexp(s[2*t][2],  SA, base1), p03 = cexp(s[2*t][3],  SA, base1);
            float p10 = cexp(s[2*t+1][0],SA, base0), p11 = cexp(s[2*t+1][1],SA, base0);
            float p12 = cexp(s[2*t+1][2],SA, base1), p13 = cexp(s[2*t+1][3],SA, base1);
            rs0 += p00 + p01 + p10 + p11;
            rs1 += p02 + p03 + p12 + p13;
            pp[t][0] = pkbf2(p00, p01);
            pp[t][1] = pkbf2(p02, p03);
            pp[t][2] = pkbf2(p10, p11);
            pp[t][3] = pkbf2(p12, p13);
        }
        rs0 += __shfl_xor_sync(0xffffffffu, rs0, 1);
        rs0 += __shfl_xor_sync(0xffffffffu, rs0, 2);
        rs1 += __shfl_xor_sync(0xffffffffu, rs1, 1);
        rs1 += __shfl_xor_sync(0xffffffffu, rs1, 2);
        l0 = l0*corr0 + rs0;
        l1 = l1*corr1 + rs1;
        #pragma unroll
        for (int j=0;j<4;j++){
            o[j][0] *= corr0; o[j][1] *= corr0;
            o[j][2] *= corr1; o[j][3] *= corr1;
        }

        // O += P V : 4 k16 steps, 4 n8 d-tiles
        #pragma unroll
        for (int t=0;t<4;t++){
            unsigned v0,v1,v2,v3, x0,x1,x2,x3;
            int vrow = 16*t + (sel & 1)*8 + r8;
            unsigned addrA = smem_u32(&Vb[vrow*40 + (sel>>1)*8]);
            unsigned addrB = smem_u32(&Vb[vrow*40 + 16 + (sel>>1)*8]);
            LDSM4T(v0,v1,v2,v3, addrA);
            LDSM4T(x0,x1,x2,x3, addrB);
            MMA16816(o[0][0],o[0][1],o[0][2],o[0][3], pp[t][0],pp[t][1],pp[t][2],pp[t][3], v0,v1);
            MMA16816(o[1][0],o[1][1],o[1][2],o[1][3], pp[t][0],pp[t][1],pp[t][2],pp[t][3], v2,v3);
            MMA16816(o[2][0],o[2][1],o[2][2],o[2][3], pp[t][0],pp[t][1],pp[t][2],pp[t][3], x0,x1);
            MMA16816(o[3][0],o[3][1],o[3][2],o[3][3], pp[t][0],pp[t][1],pp[t][2],pp[t][3], x2,x3);
        }
        __syncthreads();
    }

    // write O / l
    float rl0 = __fdividef(1.f, l0), rl1 = __fdividef(1.f, l1);
    __nv_bfloat16* Og0 = d_ATTb + ((size_t)(b*SEQ + qt*64 + w*16 + g))*256 + h*32;
    __nv_bfloat16* Og1 = Og0 + (size_t)8*256;
    #pragma unroll
    for (int j=0;j<4;j++){
        int dcol = j*8 + 2*tig;
        *(unsigned*)&Og0[dcol] = pkbf2(o[j][0]*rl0, o[j][1]*rl0);
        *(unsigned*)&Og1[dcol] = pkbf2(o[j][2]*rl1, o[j][3]*rl1);
    }
}

// ---------------- layernorm ----------------
__global__ __launch_bounds__(256) void ln_kernel(const float* __restrict__ in,
    const float* __restrict__ g, const float* __restrict__ bta, int sparse)
{
    int raw  = blockIdx.x*8 + (threadIdx.x>>5);
    int tok  = sparse ? ((raw>>7)*SEQ + 1920 + (raw&127)) : raw;
    int lane = threadIdx.x & 31;
    const float* row = in + (size_t)tok*DMODEL;
    float v[8]; float s = 0.f;
    #pragma unroll
    for (int i=0;i<8;i++){ v[i] = row[lane + i*32]; s += v[i]; }
    #pragma unroll
    for (int o=16;o>0;o>>=1) s += __shfl_xor_sync(0xffffffffu, s, o);
    float mean = s * (1.f/256.f);
    float q = 0.f;
    #pragma unroll
    for (int i=0;i<8;i++){ float d = v[i]-mean; q += d*d; }
    #pragma unroll
    for (int o=16;o>0;o>>=1) q += __shfl_xor_sync(0xffffffffu, q, o);
    float rstd = rsqrtf(q*(1.f/256.f) + 1e-5f);
    #pragma unroll
    for (int i=0;i<8;i++){
        int d_ = lane + i*32;
        float o = (v[i]-mean)*rstd*g[d_] + bta[d_];
        size_t gi = (size_t)tok*DMODEL + d_;
        d_X32[gi] = o;
        d_Xb[gi]  = __float2bfloat16(o);
    }
}

// ---------------- dec + hist + IDM + fusion ----------------
__global__ void final_kernel(const float* __restrict__ inputs,
    const float* __restrict__ his,
    const float* __restrict__ W_dec, const float* __restrict__ b_dec,
    const float* __restrict__ W_fus, const float* __restrict__ b_fus,
    float* __restrict__ out)
{
    __shared__ float dec[8], yidm[8][LOUT], lastpos[8], dvb[8];
    int tid = threadIdx.x, wid = tid>>5, lane = tid&31;
    {
        const float* row = d_X32 + ((size_t)(wid*SEQ + SEQ-1))*DMODEL;
        float s = 0.f;
        #pragma unroll
        for (int i=0;i<8;i++){ int d_ = lane + i*32; s += row[d_]*W_dec[d_]; }
        #pragma unroll
        for (int o=16;o>0;o>>=1) s += __shfl_xor_sync(0xffffffffu, s, o);
        if (lane==0) dec[wid] = s + b_dec[0];
    }
    if (tid < 8){
        int b = tid;
        float lp = inputs[((size_t)(b*SEQ + SEQ-1))*4];
        lastpos[b] = lp;
        dvb[b] = (lp - inputs[((size_t)(b*SEQ + SEQ-1-LOUT))*4]) / 50.f;
    }
    __syncthreads();

    if (tid < 8){
        int b = tid;
        const float* il = inputs + ((size_t)(b*SEQ + SEQ-1))*4;
        float y = il[0], v = il[1], sg = il[2], dv = il[3];
        const float sqab2 = 2.449489742783178f;
        float sx = 2.0f + fmaxf(0.f, v*1.5f + v*dv/sqab2);
        float t = v/30.0f; float p = t*t; p *= p;
        float rr = sx/sg;
        float af = (1.f - p - rr*rr);
        float v0 = fmaxf(v + af*0.1f, 0.f);
        float v0last = __shfl_sync(0xffu, v0, 7);
        float yp = y + v0last*0.1f;
        float vp = v0;
        yidm[b][0] = yp;
        for (int j=0;j<LOUT-1;j++){
            float hp = his[((size_t)(b*LOUT + j))*2];
            float hv = his[((size_t)(b*LOUT + j))*2 + 1];
            float dvj = hv - vp;
            float sj  = hp - yp;
            float sxj = 2.0f + fmaxf(0.f, vp*1.5f + vp*dvj/sqab2);
            float tt = vp/30.0f; float q4 = tt*tt; q4 *= q4;
            float r2 = sxj/sj;
            float acc = (1.f - q4 - r2*r2);
            float v2 = vp + acc*0.1f;
            v2 = (v2 <= 0.f) ? 0.f : v2;
            yp = yp + v2*0.1f;
            yidm[b][j+1] = yp;
            vp = v2;
        }
    }
    __syncthreads();

    float w0 = W_fus[0], w1 = W_fus[1], w2 = W_fus[2], bb = b_fus[0];
    for (int t = tid; t < BATCH*LOUT; t += 256){
        int b = t / LOUT, l = t % LOUT;
        out[t] = w0*dec[b] + w1*(lastpos[b] + dvb[b]*(float)(l+1)) + w2*yidm[b][l] + bb;
    }
}

// ---------------- launcher ----------------
extern "C" void kernel_launch(void* const* d_in, const int* in_sizes, int n_in,
                              void* d_out, int out_size)
{
    (void)in_sizes; (void)n_in; (void)out_size;
    const float* inputs = (const float*)d_in[0];
    const float* his    = (const float*)d_in[1];
    const float* W_emb  = (const float*)d_in[2];
    const float* b_emb  = (const float*)d_in[3];
    const float* Wqkv   = (const float*)d_in[4];
    const float* bqkv   = (const float*)d_in[5];
    const float* Wo     = (const float*)d_in[6];
    const float* bo     = (const float*)d_in[7];
    const float* W1     = (const float*)d_in[8];
    const float* b1     = (const float*)d_in[9];
    const float* W2     = (const float*)d_in[10];
    const float* b2     = (const float*)d_in[11];
    const float* ln1g   = (const float*)d_in[12];
    const float* ln1b   = (const float*)d_in[13];
    const float* ln2g   = (const float*)d_in[14];
    const float* ln2b   = (const float*)d_in[15];
    const float* W_dec  = (const float*)d_in[16];
    const float* b_dec  = (const float*)d_in[17];
    const float* W_fus  = (const float*)d_in[18];
    const float* b_fus  = (const float*)d_in[19];
    float* out = (float*)d_out;

    void *pXb_, *pHb_, *pWq_, *pWo_, *pW1_, *pW2_, *pATT_, *pTMP_, *pX32_;
    cudaGetSymbolAddress(&pXb_,  d_Xb);
    cudaGetSymbolAddress(&pHb_,  d_Hb);
    cudaGetSymbolAddress(&pWq_,  d_WqkvB);
    cudaGetSymbolAddress(&pWo_,  d_WoB);
    cudaGetSymbolAddress(&pW1_,  d_W1B);
    cudaGetSymbolAddress(&pW2_,  d_W2B);
    cudaGetSymbolAddress(&pATT_, d_ATTb);
    cudaGetSymbolAddress(&pTMP_, d_TMP);
    cudaGetSymbolAddress(&pX32_, d_X32);

    __nv_bfloat16* Xb   = (__nv_bfloat16*)pXb_;
    __nv_bfloat16* Hb   = (__nv_bfloat16*)pHb_;
    __nv_bfloat16* WqB  = (__nv_bfloat16*)pWq_;
    __nv_bfloat16* WoB  = (__nv_bfloat16*)pWo_;
    __nv_bfloat16* W1B  = (__nv_bfloat16*)pW1_;
    __nv_bfloat16* W2B  = (__nv_bfloat16*)pW2_;
    __nv_bfloat16* ATTb = (__nv_bfloat16*)pATT_;
    float*         TMP  = (float*)pTMP_;
    float*         X32  = (float*)pX32_;
    __nv_bfloat16* QKVb;
    { void* p; cudaGetSymbolAddress(&p, d_QKVb); QKVb = (__nv_bfloat16*)p; }

    conv_kernel<<<(NLAY*768*256+255)/256, 256>>>(Wqkv, WqB, NLAY*768*256);
    conv_kernel<<<(NLAY*256*256+255)/256, 256>>>(Wo,   WoB, NLAY*256*256);
    conv_kernel<<<(NLAY*1024*256+255)/256,256>>>(W1,   W1B, NLAY*1024*256);
    conv_kernel<<<(NLAY*256*1024+255)/256,256>>>(W2,   W2B, NLAY*256*1024);

    embed_kernel<<<NTOK, 256>>>(inputs, W_emb, b_emb);

    for (int l = 0; l < NLAY; l++){
        int sp      = (l == NLAY-1);
        int gridY   = sp ? 8  : 128;
        int mStride = sp ? 16 : 1;
        int mOff    = sp ? 15 : 0;

        gemm_kernel<<<dim3(6,128), 256>>>(Xb, WqB + (size_t)l*768*256,
            bqkv + l*768, nullptr, nullptr, QKVb, 768, 256, 0, 1, 0);

        if (!sp) attn_kernel<<<dim3(32,64), 128>>>(0);
        else     attn_kernel<<<dim3(1,64),  128>>>(31);

        gemm_kernel<<<dim3(2,gridY), 256>>>(ATTb, WoB + (size_t)l*256*256,
            bo + l*256, X32, TMP, nullptr, 256, 256, 0, mStride, mOff);

        ln_kernel<<<sp?128:2048, 256>>>(TMP, ln1g + l*256, ln1b + l*256, sp);

        gemm_kernel<<<dim3(8,gridY), 256>>>(Xb, W1B + (size_t)l*1024*256,
            b1 + l*1024, nullptr, nullptr, Hb, 1024, 256, 1, mStride, mOff);

        gemm_kernel<<<dim3(2,gridY), 256>>>(Hb, W2B + (size_t)l*256*1024,
            b2 + l*256, X32, TMP, nullptr, 256, 1024, 0, mStride, mOff);

        ln_kernel<<<sp?128:2048, 256>>>(TMP, ln2g + l*256, ln2b + l*256, sp);
    }

    final_kernel<<<1, 256>>>(inputs, his, W_dec, b_dec, W_fus, b_fus, out);
}

// round 5
// speedup vs baseline: 3.5526x; 1.0253x over previous
#include <cuda_runtime.h>
#include <cuda_bf16.h>
#include <mma.h>

using namespace nvcuda;

// ---------------- problem constants ----------------
#define BATCH   8
#define SEQ     2048
#define DMODEL  256
#define NHEAD   8
#define DHEAD   32
#define NHID    1024
#define NLAY    4
#define NTOK    (BATCH*SEQ)        // 16384
#define LOUT    50
#define ATT_SCALE 0.17677669529663687f   // 1/sqrt(32)

// ---------------- scratch ----------------
__device__ __align__(256) float          d_X32 [NTOK*DMODEL];
__device__ __align__(256) __nv_bfloat16  d_Xb  [NTOK*DMODEL];
__device__ __align__(256) __nv_bfloat16  d_QKVb[NTOK*3*DMODEL];
__device__ __align__(256) __nv_bfloat16  d_ATTb[NTOK*DMODEL];
__device__ __align__(256) __nv_bfloat16  d_Hb  [NTOK*NHID];
__device__ __align__(256) __nv_bfloat16  d_WqkvB[NLAY*3*DMODEL*DMODEL];
__device__ __align__(256) __nv_bfloat16  d_WoB  [NLAY*DMODEL*DMODEL];
__device__ __align__(256) __nv_bfloat16  d_W1B  [NLAY*NHID*DMODEL];
__device__ __align__(256) __nv_bfloat16  d_W2B  [NLAY*DMODEL*NHID];
__device__ __align__(256) float          d_u[768];
__device__ __align__(256) float          d_c[768];

// ---------------- PTX helpers ----------------
__device__ __forceinline__ unsigned smem_u32(const void* p){
    return (unsigned)__cvta_generic_to_shared(p);
}
#define CPA(dst, src) asm volatile("cp.async.cg.shared.global [%0], [%1], 16;" :: "r"(dst), "l"(src))
#define CPC() asm volatile("cp.async.commit_group;")
#define CPW0() asm volatile("cp.async.wait_group 0;")
#define CPW1() asm volatile("cp.async.wait_group 1;")
#define LDSM4(r0,r1,r2,r3,a) asm volatile("ldmatrix.sync.aligned.m8n8.x4.shared.b16 {%0,%1,%2,%3}, [%4];" \
    : "=r"(r0),"=r"(r1),"=r"(r2),"=r"(r3) : "r"(a))
#define LDSM4T(r0,r1,r2,r3,a) asm volatile("ldmatrix.sync.aligned.m8n8.x4.trans.shared.b16 {%0,%1,%2,%3}, [%4];" \
    : "=r"(r0),"=r"(r1),"=r"(r2),"=r"(r3) : "r"(a))
#define MMA16816(d0,d1,d2,d3, a0,a1,a2,a3, b0,b1) \
    asm volatile("mma.sync.aligned.m16n8k16.row.col.f32.bf16.bf16.f32 " \
        "{%0,%1,%2,%3}, {%4,%5,%6,%7}, {%8,%9}, {%0,%1,%2,%3};" \
        : "+f"(d0),"+f"(d1),"+f"(d2),"+f"(d3) \
        : "r"(a0),"r"(a1),"r"(a2),"r"(a3), "r"(b0),"r"(b1))

__device__ __forceinline__ unsigned pkbf2(float lo, float hi){
    unsigned d;
    asm("cvt.rn.bf16x2.f32 %0, %1, %2;" : "=r"(d) : "f"(hi), "f"(lo));
    return d;
}
// Schraudolph exp(EXP_SA_raw*(s) + base-style); clamped so very-negative args -> 0
#define EXP_B0 1064986316.0f
#define EXP_SA (12102203.161f * ATT_SCALE)
__device__ __forceinline__ float cexpb(float s, float base){
    float t = fmaf(s, EXP_SA, base);
    t = fmaxf(t, 0.f);
    return __int_as_float((int)t);
}

// ---------------- merged weight conversion (all 4 weight groups) ----------------
#define N0 (NLAY*768*256)
#define N1 (NLAY*256*256)
#define N2 (NLAY*NHID*256)
#define N3 (NLAY*256*NHID)
__global__ void conv4_kernel(const float* __restrict__ s0, const float* __restrict__ s1,
                             const float* __restrict__ s2, const float* __restrict__ s3)
{
    int i = (blockIdx.x*blockDim.x + threadIdx.x)*4;
    const float* s; __nv_bfloat16* d;
    if      (i < N0)         { s = s0 + i;              d = d_WqkvB + i; }
    else if (i < N0+N1)      { s = s1 + (i-N0);         d = d_WoB  + (i-N0); }
    else if (i < N0+N1+N2)   { s = s2 + (i-N0-N1);      d = d_W1B  + (i-N0-N1); }
    else                     { s = s3 + (i-N0-N1-N2);   d = d_W2B  + (i-N0-N1-N2); }
    float4 v = *(const float4*)s;
    uint2 o; o.x = pkbf2(v.x, v.y); o.y = pkbf2(v.z, v.w);
    *(uint2*)d = o;
}

// ---------------- rank-1 layer-0 QKV precompute ----------------
__global__ void prep0_kernel(const float* __restrict__ Wqkv, const float* __restrict__ bqkv,
                             const float* __restrict__ W_emb, const float* __restrict__ b_emb)
{
    int wid = threadIdx.x >> 5, lane = threadIdx.x & 31;
    for (int j = wid; j < 768; j += 8){
        const float* row = Wqkv + (size_t)j*256;
        float su = 0.f, sc = 0.f;
        #pragma unroll
        for (int i=0;i<8;i++){
            float w = row[lane + i*32];
            su = fmaf(w, W_emb[lane + i*32], su);
            sc = fmaf(w, b_emb[lane + i*32], sc);
        }
        #pragma unroll
        for (int o=16;o>0;o>>=1){
            su += __shfl_xor_sync(0xffffffffu, su, o);
            sc += __shfl_xor_sync(0xffffffffu, sc, o);
        }
        if (lane == 0){ d_u[j] = su; d_c[j] = sc + bqkv[j]; }
    }
}

// ---------------- embed + layer-0 QKV (rank-1) ----------------
__global__ void embed0_kernel(const float* __restrict__ inputs,
                              const float* __restrict__ W_emb,
                              const float* __restrict__ b_emb)
{
    int tok = blockIdx.x;
    int d   = threadIdx.x;
    float y = __ldg(&inputs[(size_t)tok*4]);
    float v = fmaf(y, W_emb[d], b_emb[d]);
    size_t gi = (size_t)tok*DMODEL + d;
    d_X32[gi] = v;
    d_Xb[gi]  = __float2bfloat16(v);
    #pragma unroll
    for (int t=0;t<3;t++){
        int j = d + t*256;
        float q = fmaf(y, d_u[j], d_c[j]);
        d_QKVb[(size_t)tok*768 + j] = __float2bfloat16(q);
    }
}

// ---------------- GEMM: C = A(MxK) * B(NxK)^T + bias [relu] -> bf16 ----------------
// tile 128x128, BK=32, cp.async double buffered, 8 warps 4x2 each 32x64
__global__ __launch_bounds__(256) void gemm_kernel(
    const __nv_bfloat16* __restrict__ A,
    const __nv_bfloat16* __restrict__ B,
    const float* __restrict__ bias,
    __nv_bfloat16* __restrict__ outB,
    int N, int K, int relu, int mStride, int mOff)
{
    __shared__ __align__(16) unsigned char sm_raw[41088];
    __nv_bfloat16* As = (__nv_bfloat16*)sm_raw;      // [2][128*40]
    __nv_bfloat16* Bs = As + 2*128*40;               // [2][128*40]
    float*         Cs = (float*)sm_raw;              // 64*136

    const int tid = threadIdx.x;
    const int wid = tid >> 5;
    const int wm  = wid >> 1, wn = wid & 1;
    const int m0  = (blockIdx.y * mStride + mOff) * 128;
    const int n0  = blockIdx.x * 128;

    wmma::fragment<wmma::accumulator,16,16,16,float> cf[2][4];
    #pragma unroll
    for (int i=0;i<2;i++)
        #pragma unroll
        for (int j=0;j<4;j++) wmma::fill_fragment(cf[i][j], 0.f);

    const int kIter = K >> 5;

    auto issue = [&](int i, int bf){
        const __nv_bfloat16* Ag = A + (size_t)m0*K + i*32;
        const __nv_bfloat16* Bg = B + (size_t)n0*K + i*32;
        __nv_bfloat16* Ad = As + bf*5120;
        __nv_bfloat16* Bd = Bs + bf*5120;
        #pragma unroll
        for (int c = tid; c < 512; c += 256){
            int r = c >> 2, off = (c & 3)*8;
            CPA(smem_u32(&Ad[r*40+off]), Ag + (size_t)r*K + off);
            CPA(smem_u32(&Bd[r*40+off]), Bg + (size_t)r*K + off);
        }
    };

    issue(0, 0); CPC();
    for (int i = 0; i < kIter; i++){
        int buf = i & 1;
        if (i+1 < kIter){ issue(i+1, (i+1)&1); CPC(); CPW1(); }
        else            { CPW0(); }
        __syncthreads();
        const __nv_bfloat16* Asb = As + buf*5120;
        const __nv_bfloat16* Bsb = Bs + buf*5120;
        #pragma unroll
        for (int kk = 0; kk < 32; kk += 16){
            wmma::fragment<wmma::matrix_a,16,16,16,__nv_bfloat16,wmma::row_major> af[2];
            wmma::fragment<wmma::matrix_b,16,16,16,__nv_bfloat16,wmma::col_major> bfr[4];
            #pragma unroll
            for (int x=0;x<2;x++) wmma::load_matrix_sync(af[x],  &Asb[(wm*32 + x*16)*40 + kk], 40);
            #pragma unroll
            for (int j=0;j<4;j++) wmma::load_matrix_sync(bfr[j], &Bsb[(wn*64 + j*16)*40 + kk], 40);
            #pragma unroll
            for (int x=0;x<2;x++)
                #pragma unroll
                for (int j=0;j<4;j++)
                    wmma::mma_sync(cf[x][j], af[x], bfr[j], cf[x][j]);
        }
        __syncthreads();
    }

    #pragma unroll
    for (int chunk = 0; chunk < 2; chunk++){
        if ((wm >> 1) == chunk){
            #pragma unroll
            for (int x=0;x<2;x++)
                #pragma unroll
                for (int j=0;j<4;j++)
                    wmma::store_matrix_sync(&Cs[((wm&1)*32 + x*16)*136 + wn*64 + j*16],
                                            cf[x][j], 136, wmma::mem_row_major);
        }
        __syncthreads();
        for (int e = tid; e < 64*128; e += 256){
            int cm = e >> 7, cn = e & 127;
            float v = Cs[cm*136+cn] + bias[n0+cn];
            if (relu) v = fmaxf(v, 0.f);
            outB[(size_t)(m0 + chunk*64 + cm)*N + n0 + cn] = __float2bfloat16(v);
        }
        __syncthreads();
    }
}

// ---------------- GEMM + bias + resid + LayerNorm fused epilogue ----------------
// C = LN( A(MxK) @ B(256xK)^T + bias + X32 ) -> d_X32 (fp32) and d_Xb (bf16)
// tile 64x256, BK=32.  A: cp.async double buffered.  B: single smem buffer,
// next k-step staged through registers.  smem = 33792 B (< 48K static cap)
__global__ __launch_bounds__(256) void gemm_ln_kernel(
    const __nv_bfloat16* __restrict__ A,
    const __nv_bfloat16* __restrict__ B,
    const float* __restrict__ bias,
    const float* __restrict__ g,
    const float* __restrict__ bta,
    int K, int sparse)
{
    __shared__ __align__(16) unsigned char sm_raw[33792];
    __nv_bfloat16* As = (__nv_bfloat16*)sm_raw;      // [2][64*40]  = 10240 B
    __nv_bfloat16* Bs = As + 2*64*40;                // [256*40]    = 20480 B
    float*         Cs = (float*)sm_raw;              // [32][264]   = 33792 B

    const int tid = threadIdx.x;
    const int wid = tid >> 5, lane = tid & 31;
    const int wm  = wid >> 2, wn = wid & 3;
    const int t64 = sparse ? ((blockIdx.y >> 1)*32 + 30 + (blockIdx.y & 1)) : blockIdx.y;
    const int m0  = t64 * 64;

    int br[4], boff[4];
    #pragma unroll
    for (int j=0;j<4;j++){ int c = tid + j*256; br[j] = c >> 2; boff[j] = (c & 3)*8; }

    wmma::fragment<wmma::accumulator,16,16,16,float> cf[2][4];
    #pragma unroll
    for (int i=0;i<2;i++)
        #pragma unroll
        for (int j=0;j<4;j++) wmma::fill_fragment(cf[i][j], 0.f);

    const int kIter = K >> 5;

    auto issueA = [&](int i, int bf){
        const __nv_bfloat16* Ag = A + (size_t)m0*K + i*32;
        __nv_bfloat16* Ad = As + bf*(64*40);
        int r = tid >> 2, off = (tid & 3)*8;
        CPA(smem_u32(&Ad[r*40+off]), Ag + (size_t)r*K + off);
    };

    issueA(0, 0);
    #pragma unroll
    for (int j=0;j<4;j++)
        CPA(smem_u32(&Bs[br[j]*40+boff[j]]), B + (size_t)br[j]*K + boff[j]);
    CPC(); CPW0();
    __syncthreads();

    for (int i = 0; i < kIter; i++){
        int buf = i & 1;
        bool more = (i+1 < kIter);
        uint4 breg[4];
        if (more){
            const __nv_bfloat16* Bg = B + (i+1)*32;
            #pragma unroll
            for (int j=0;j<4;j++)
                breg[j] = *(const uint4*)(Bg + (size_t)br[j]*K + boff[j]);
            issueA(i+1, buf ^ 1); CPC();
        }
        const __nv_bfloat16* Asb = As + buf*(64*40);
        #pragma unroll
        for (int kk = 0; kk < 32; kk += 16){
            wmma::fragment<wmma::matrix_a,16,16,16,__nv_bfloat16,wmma::row_major> af[2];
            wmma::fragment<wmma::matrix_b,16,16,16,__nv_bfloat16,wmma::col_major> bfr[4];
            #pragma unroll
            for (int x=0;x<2;x++) wmma::load_matrix_sync(af[x],  &Asb[(wm*32 + x*16)*40 + kk], 40);
            #pragma unroll
            for (int j=0;j<4;j++) wmma::load_matrix_sync(bfr[j], &Bs[(wn*64 + j*16)*40 + kk], 40);
            #pragma unroll
            for (int x=0;x<2;x++)
                #pragma unroll
                for (int j=0;j<4;j++)
                    wmma::mma_sync(cf[x][j], af[x], bfr[j], cf[x][j]);
        }
        __syncthreads();
        if (more){
            #pragma unroll
            for (int j=0;j<4;j++)
                *(uint4*)&Bs[br[j]*40+boff[j]] = breg[j];
            CPW0();
        }
        __syncthreads();
    }

    #pragma unroll
    for (int chunk = 0; chunk < 2; chunk++){
        if (wm == chunk){
            #pragma unroll
            for (int x=0;x<2;x++)
                #pragma unroll
                for (int j=0;j<4;j++)
                    wmma::store_matrix_sync(&Cs[(x*16)*264 + wn*64 + j*16],
                                            cf[x][j], 264, wmma::mem_row_major);
        }
        __syncthreads();
        #pragma unroll
        for (int ii=0; ii<4; ii++){
            int rloc = wid*4 + ii;
            int tok  = m0 + chunk*32 + rloc;
            float v[8]; float s = 0.f;
            #pragma unroll
            for (int i=0;i<8;i++){
                int c = lane + i*32;
                v[i] = Cs[rloc*264 + c] + bias[c] + d_X32[(size_t)tok*DMODEL + c];
                s += v[i];
            }
            #pragma unroll
            for (int o=16;o>0;o>>=1) s += __shfl_xor_sync(0xffffffffu, s, o);
            float mean = s * (1.f/256.f);
            float q = 0.f;
            #pragma unroll
            for (int i=0;i<8;i++){ float dd = v[i]-mean; q = fmaf(dd, dd, q); }
            #pragma unroll
            for (int o=16;o>0;o>>=1) q += __shfl_xor_sync(0xffffffffu, q, o);
            float rstd = rsqrtf(q*(1.f/256.f) + 1e-5f);
            #pragma unroll
            for (int i=0;i<8;i++){
                int c = lane + i*32;
                float o = (v[i]-mean)*rstd*g[c] + bta[c];
                size_t gi = (size_t)tok*DMODEL + c;
                d_X32[gi] = o;
                d_Xb[gi]  = __float2bfloat16(o);
            }
        }
        __syncthreads();
    }
}

// ---------------- flash attention: 128 q rows / block (8 warps) ----------------
// useMax=1: running-max softmax (layer 0: un-normalized inputs -> huge scores)
// useMax=0: fixed-base Schraudolph softmax (layers 1-3: LN'd inputs, |s*scale|<~1)
__global__ __launch_bounds__(256) void attn_kernel(int qtOffset, int useMax)
{
    __shared__ __align__(16) __nv_bfloat16 Qs[128*40];
    __shared__ __align__(16) __nv_bfloat16 Ks[2][64*40];
    __shared__ __align__(16) __nv_bfloat16 Vs[2][64*40];

    const int tid = threadIdx.x, lane = tid & 31, w = tid >> 5;
    const int qt = blockIdx.x + qtOffset;              // 128-row q tile
    const int bh = blockIdx.y, b = bh >> 3, h = bh & 7;
    const int g = lane >> 2, tig = lane & 3;
    const int r8 = lane & 7, sel = lane >> 3;
    const int rwBase = qt*128 + w*16;                  // warp's first global q row

    // prologue: Q + KV tile 0 via cp.async
    const __nv_bfloat16* Qg = d_QKVb + ((size_t)(b*SEQ + qt*128))*768 + h*32;
    #pragma unroll
    for (int c = tid; c < 512; c += 256){
        int r = c >> 2, off = (c & 3)*8;
        CPA(smem_u32(&Qs[r*40+off]), Qg + (size_t)r*768 + off);
    }
    {
        const __nv_bfloat16* Kg = d_QKVb + ((size_t)(b*SEQ))*768 + 256 + h*32;
        const __nv_bfloat16* Vg = Kg + 256;
        int c = tid, r = c >> 2, off = (c & 3)*8;
        CPA(smem_u32(&Ks[0][r*40+off]), Kg + (size_t)r*768 + off);
        CPA(smem_u32(&Vs[0][r*40+off]), Vg + (size_t)r*768 + off);
    }
    CPC(); CPW0();
    __syncthreads();

    unsigned aq[2][4];
    {
        int row = w*16 + (sel & 1)*8 + r8;
        #pragma unroll
        for (int t=0;t<2;t++){
            unsigned addr = smem_u32(&Qs[row*40 + t*16 + (sel>>1)*8]);
            LDSM4(aq[t][0], aq[t][1], aq[t][2], aq[t][3], addr);
        }
    }

    float o[4][4];
    #pragma unroll
    for (int j=0;j<4;j++){ o[j][0]=0.f;o[j][1]=0.f;o[j][2]=0.f;o[j][3]=0.f; }
    float l0 = 0.f, l1 = 0.f;
    float m0v = -1e30f, m1v = -1e30f;        // running max (useMax only)
    const int gr0 = rwBase + g;              // global rows gr0, gr0+8

    const int kmax = 2*qt + 1;
    for (int kt2 = 0; kt2 <= kmax; kt2++){
        int buf = kt2 & 1;
        if (kt2 < kmax){
            int nb = buf ^ 1;
            const __nv_bfloat16* Kg = d_QKVb + ((size_t)(b*SEQ + (kt2+1)*64))*768 + 256 + h*32;
            const __nv_bfloat16* Vg = Kg + 256;
            int c = tid, r = c >> 2, off = (c & 3)*8;
            CPA(smem_u32(&Ks[nb][r*40+off]), Kg + (size_t)r*768 + off);
            CPA(smem_u32(&Vs[nb][r*40+off]), Vg + (size_t)r*768 + off);
            CPC(); CPW1();
        } else {
            CPW0();
        }
        __syncthreads();

        const int cb = kt2*64;
        if (cb <= rwBase + 15){   // warp has at least one unmasked row
            const __nv_bfloat16* Kb = Ks[buf];
            const __nv_bfloat16* Vb = Vs[buf];

            // S = Q K^T
            float s[8][4];
            #pragma unroll
            for (int j=0;j<8;j++){
                s[j][0]=0.f;s[j][1]=0.f;s[j][2]=0.f;s[j][3]=0.f;
                unsigned k0,k1,k2,k3;
                unsigned addr = smem_u32(&Kb[(j*8 + r8)*40 + sel*8]);
                LDSM4(k0,k1,k2,k3, addr);
                MMA16816(s[j][0],s[j][1],s[j][2],s[j][3],
                         aq[0][0],aq[0][1],aq[0][2],aq[0][3], k0,k1);
                MMA16816(s[j][0],s[j][1],s[j][2],s[j][3],
                         aq[1][0],aq[1][1],aq[1][2],aq[1][3], k2,k3);
            }

            if (cb + 63 > rwBase){   // diagonal overlap: mask
                #pragma unroll
                for (int j=0;j<8;j++){
                    int c0 = cb + j*8 + 2*tig;
                    if (c0   > gr0)   s[j][0] = -1e30f;
                    if (c0+1 > gr0)   s[j][1] = -1e30f;
                    if (c0   > gr0+8) s[j][2] = -1e30f;
                    if (c0+1 > gr0+8) s[j][3] = -1e30f;
                }
            }

            float base0 = EXP_B0, base1 = EXP_B0;
            if (useMax){
                float mt0 = -1e30f, mt1 = -1e30f;
                #pragma unroll
                for (int j=0;j<8;j++){
                    mt0 = fmaxf(mt0, fmaxf(s[j][0], s[j][1]));
                    mt1 = fmaxf(mt1, fmaxf(s[j][2], s[j][3]));
                }
                mt0 = fmaxf(mt0, __shfl_xor_sync(0xffffffffu, mt0, 1));
                mt0 = fmaxf(mt0, __shfl_xor_sync(0xffffffffu, mt0, 2));
                mt1 = fmaxf(mt1, __shfl_xor_sync(0xffffffffu, mt1, 1));
                mt1 = fmaxf(mt1, __shfl_xor_sync(0xffffffffu, mt1, 2));
                float nm0 = fmaxf(m0v, mt0), nm1 = fmaxf(m1v, mt1);
                base0 = EXP_B0 - EXP_SA*nm0;
                base1 = EXP_B0 - EXP_SA*nm1;
                float corr0 = cexpb(m0v, base0), corr1 = cexpb(m1v, base1);
                m0v = nm0; m1v = nm1;
                l0 *= corr0; l1 *= corr1;
                #pragma unroll
                for (int j=0;j<4;j++){
                    o[j][0] *= corr0; o[j][1] *= corr0;
                    o[j][2] *= corr1; o[j][3] *= corr1;
                }
            }

            // exp, accumulate l locally (base row-uniform across quad), pack P
            unsigned pp[4][4];
            #pragma unroll
            for (int t=0;t<4;t++){
                float p00 = cexpb(s[2*t][0],   base0), p01 = cexpb(s[2*t][1],   base0);
                float p02 = cexpb(s[2*t][2],   base1), p03 = cexpb(s[2*t][3],   base1);
                float p10 = cexpb(s[2*t+1][0], base0), p11 = cexpb(s[2*t+1][1], base0);
                float p12 = cexpb(s[2*t+1][2], base1), p13 = cexpb(s[2*t+1][3], base1);
                l0 += p00 + p01 + p10 + p11;
                l1 += p02 + p03 + p12 + p13;
                pp[t][0] = pkbf2(p00, p01);
                pp[t][1] = pkbf2(p02, p03);
                pp[t][2] = pkbf2(p10, p11);
                pp[t][3] = pkbf2(p12, p13);
            }

            // O += P V
            #pragma unroll
            for (int t=0;t<4;t++){
                unsigned v0,v1,v2,v3, x0,x1,x2,x3;
                int vrow = 16*t + (sel & 1)*8 + r8;
                unsigned addrA = smem_u32(&Vb[vrow*40 + (sel>>1)*8]);
                unsigned addrB = smem_u32(&Vb[vrow*40 + 16 + (sel>>1)*8]);
                LDSM4T(v0,v1,v2,v3, addrA);
                LDSM4T(x0,x1,x2,x3, addrB);
                MMA16816(o[0][0],o[0][1],o[0][2],o[0][3], pp[t][0],pp[t][1],pp[t][2],pp[t][3], v0,v1);
                MMA16816(o[1][0],o[1][1],o[1][2],o[1][3], pp[t][0],pp[t][1],pp[t][2],pp[t][3], v2,v3);
                MMA16816(o[2][0],o[2][1],o[2][2],o[2][3], pp[t][0],pp[t][1],pp[t][2],pp[t][3], x0,x1);
                MMA16816(o[3][0],o[3][1],o[3][2],o[3][3], pp[t][0],pp[t][1],pp[t][2],pp[t][3], x2,x3);
            }
        }
        __syncthreads();
    }

    // final l reduction across quad, write O
    l0 += __shfl_xor_sync(0xffffffffu, l0, 1);
    l0 += __shfl_xor_sync(0xffffffffu, l0, 2);
    l1 += __shfl_xor_sync(0xffffffffu, l1, 1);
    l1 += __shfl_xor_sync(0xffffffffu, l1, 2);
    float rl0 = __fdividef(1.f, l0), rl1 = __fdividef(1.f, l1);
    __nv_bfloat16* Og0 = d_ATTb + ((size_t)(b*SEQ + rwBase + g))*256 + h*32;
    __nv_bfloat16* Og1 = Og0 + (size_t)8*256;
    #pragma unroll
    for (int j=0;j<4;j++){
        int dcol = j*8 + 2*tig;
        *(unsigned*)&Og0[dcol] = pkbf2(o[j][0]*rl0, o[j][1]*rl0);
        *(unsigned*)&Og1[dcol] = pkbf2(o[j][2]*rl1, o[j][3]*rl1);
    }
}

// ---------------- dec + hist + IDM + fusion ----------------
__global__ void final_kernel(const float* __restrict__ inputs,
    const float* __restrict__ his,
    const float* __restrict__ W_dec, const float* __restrict__ b_dec,
    const float* __restrict__ W_fus, const float* __restrict__ b_fus,
    float* __restrict__ out)
{
    __shared__ float dec[8], yidm[8][LOUT], lastpos[8], dvb[8];
    int tid = threadIdx.x, wid = tid>>5, lane = tid&31;
    {
        const float* row = d_X32 + ((size_t)(wid*SEQ + SEQ-1))*DMODEL;
        float s = 0.f;
        #pragma unroll
        for (int i=0;i<8;i++){ int d_ = lane + i*32; s += row[d_]*W_dec[d_]; }
        #pragma unroll
        for (int o=16;o>0;o>>=1) s += __shfl_xor_sync(0xffffffffu, s, o);
        if (lane==0) dec[wid] = s + b_dec[0];
    }
    if (tid < 8){
        int b = tid;
        float lp = inputs[((size_t)(b*SEQ + SEQ-1))*4];
        lastpos[b] = lp;
        dvb[b] = (lp - inputs[((size_t)(b*SEQ + SEQ-1-LOUT))*4]) / 50.f;
    }
    __syncthreads();

    if (tid < 8){
        int b = tid;
        const float* il = inputs + ((size_t)(b*SEQ + SEQ-1))*4;
        float y = il[0], v = il[1], sg = il[2], dv = il[3];
        const float sqab2 = 2.449489742783178f;
        float sx = 2.0f + fmaxf(0.f, v*1.5f + v*dv/sqab2);
        float t = v/30.0f; float p = t*t; p *= p;
        float rr = sx/sg;
        float af = (1.f - p - rr*rr);
        float v0 = fmaxf(v + af*0.1f, 0.f);
        float v0last = __shfl_sync(0xffu, v0, 7);   // reference's v0[-1] broadcast
        float yp = y + v0last*0.1f;
        float vp = v0;
        yidm[b][0] = yp;
        for (int j=0;j<LOUT-1;j++){
            float hp = his[((size_t)(b*LOUT + j))*2];
            float hv = his[((size_t)(b*LOUT + j))*2 + 1];
            float dvj = hv - vp;
            float sj  = hp - yp;
            float sxj = 2.0f + fmaxf(0.f, vp*1.5f + vp*dvj/sqab2);
            float tt = vp/30.0f; float q4 = tt*tt; q4 *= q4;
            float r2 = sxj/sj;
            float acc = (1.f - q4 - r2*r2);
            float v2 = vp + acc*0.1f;
            v2 = (v2 <= 0.f) ? 0.f : v2;
            yp = yp + v2*0.1f;
            yidm[b][j+1] = yp;
            vp = v2;
        }
    }
    __syncthreads();

    float w0 = W_fus[0], w1 = W_fus[1], w2 = W_fus[2], bb = b_fus[0];
    for (int t = tid; t < BATCH*LOUT; t += 256){
        int b = t / LOUT, l = t % LOUT;
        out[t] = w0*dec[b] + w1*(lastpos[b] + dvb[b]*(float)(l+1)) + w2*yidm[b][l] + bb;
    }
}

// ---------------- launcher ----------------
extern "C" void kernel_launch(void* const* d_in, const int* in_sizes, int n_in,
                              void* d_out, int out_size)
{
    (void)in_sizes; (void)n_in; (void)out_size;
    const float* inputs = (const float*)d_in[0];
    const float* his    = (const float*)d_in[1];
    const float* W_emb  = (const float*)d_in[2];
    const float* b_emb  = (const float*)d_in[3];
    const float* Wqkv   = (const float*)d_in[4];
    const float* bqkv   = (const float*)d_in[5];
    const float* Wo     = (const float*)d_in[6];
    const float* bo     = (const float*)d_in[7];
    const float* W1     = (const float*)d_in[8];
    const float* b1     = (const float*)d_in[9];
    const float* W2     = (const float*)d_in[10];
    const float* b2     = (const float*)d_in[11];
    const float* ln1g   = (const float*)d_in[12];
    const float* ln1b   = (const float*)d_in[13];
    const float* ln2g   = (const float*)d_in[14];
    const float* ln2b   = (const float*)d_in[15];
    const float* W_dec  = (const float*)d_in[16];
    const float* b_dec  = (const float*)d_in[17];
    const float* W_fus  = (const float*)d_in[18];
    const float* b_fus  = (const float*)d_in[19];
    float* out = (float*)d_out;

    void *pXb_, *pHb_, *pWq_, *pWo_, *pW1_, *pW2_, *pATT_, *pQKV_;
    cudaGetSymbolAddress(&pXb_,  d_Xb);
    cudaGetSymbolAddress(&pHb_,  d_Hb);
    cudaGetSymbolAddress(&pWq_,  d_WqkvB);
    cudaGetSymbolAddress(&pWo_,  d_WoB);
    cudaGetSymbolAddress(&pW1_,  d_W1B);
    cudaGetSymbolAddress(&pW2_,  d_W2B);
    cudaGetSymbolAddress(&pATT_, d_ATTb);
    cudaGetSymbolAddress(&pQKV_, d_QKVb);

    __nv_bfloat16* Xb   = (__nv_bfloat16*)pXb_;
    __nv_bfloat16* Hb   = (__nv_bfloat16*)pHb_;
    __nv_bfloat16* WqB  = (__nv_bfloat16*)pWq_;
    __nv_bfloat16* WoB  = (__nv_bfloat16*)pWo_;
    __nv_bfloat16* W1B  = (__nv_bfloat16*)pW1_;
    __nv_bfloat16* W2B  = (__nv_bfloat16*)pW2_;
    __nv_bfloat16* ATTb = (__nv_bfloat16*)pATT_;
    __nv_bfloat16* QKVb = (__nv_bfloat16*)pQKV_;

    conv4_kernel<<<(N0+N1+N2+N3)/4/256, 256>>>(Wqkv, Wo, W1, W2);
    prep0_kernel<<<1, 256>>>(Wqkv, bqkv, W_emb, b_emb);
    embed0_kernel<<<NTOK, 256>>>(inputs, W_emb, b_emb);

    for (int l = 0; l < NLAY; l++){
        int sp = (l == NLAY-1);
        int useMax = (l == 0);

        if (l > 0)
            gemm_kernel<<<dim3(6,128), 256>>>(Xb, WqB + (size_t)l*768*256,
                bqkv + l*768, QKVb, 768, 256, 0, 1, 0);

        if (!sp) attn_kernel<<<dim3(16,64), 256>>>(0, useMax);
        else     attn_kernel<<<dim3(1,64),  256>>>(15, useMax);

        // Wo + resid + LN1 fused
        gemm_ln_kernel<<<dim3(1, sp?16:256), 256>>>(ATTb, WoB + (size_t)l*256*256,
            bo + l*256, ln1g + l*256, ln1b + l*256, 256, sp);

        // FFN1 relu
        gemm_kernel<<<dim3(8, sp?8:128), 256>>>(Xb, W1B + (size_t)l*1024*256,
            b1 + l*1024, Hb, 1024, 256, 1, sp?16:1, sp?15:0);

        // FFN2 + resid + LN2 fused
        gemm_ln_kernel<<<dim3(1, sp?16:256), 256>>>(Hb, W2B + (size_t)l*256*1024,
            b2 + l*256, ln2g + l*256, ln2b + l*256, 1024, sp);
    }

    final_kernel<<<1, 256>>>(inputs, his, W_dec, b_dec, W_fus, b_fus, out);
}

// round 6
// speedup vs baseline: 3.9287x; 1.1059x over previous
#include <cuda_runtime.h>
#include <cuda_bf16.h>
#include <mma.h>

using namespace nvcuda;

// ---------------- problem constants ----------------
#define BATCH   8
#define SEQ     2048
#define DMODEL  256
#define NHEAD   8
#define DHEAD   32
#define NHID    1024
#define NLAY    4
#define NTOK    (BATCH*SEQ)        // 16384
#define LOUT    50
#define ATT_SCALE 0.17677669529663687f   // 1/sqrt(32)

// ---------------- scratch ----------------
__device__ __align__(256) float          d_X32 [NTOK*DMODEL];
__device__ __align__(256) __nv_bfloat16  d_Xb  [NTOK*DMODEL];
__device__ __align__(256) __nv_bfloat16  d_QKVb[NTOK*3*DMODEL];
__device__ __align__(256) __nv_bfloat16  d_ATTb[NTOK*DMODEL];
__device__ __align__(256) __nv_bfloat16  d_Hb  [NTOK*NHID];
__device__ __align__(256) __nv_bfloat16  d_WqkvB[NLAY*3*DMODEL*DMODEL];
__device__ __align__(256) __nv_bfloat16  d_WoB  [NLAY*DMODEL*DMODEL];
__device__ __align__(256) __nv_bfloat16  d_W1B  [NLAY*NHID*DMODEL];
__device__ __align__(256) __nv_bfloat16  d_W2B  [NLAY*DMODEL*NHID];
__device__ __align__(256) float          d_u[768];
__device__ __align__(256) float          d_c[768];

// ---------------- PTX helpers ----------------
__device__ __forceinline__ unsigned smem_u32(const void* p){
    return (unsigned)__cvta_generic_to_shared(p);
}
#define CPA(dst, src) asm volatile("cp.async.cg.shared.global [%0], [%1], 16;" :: "r"(dst), "l"(src))
#define CPC() asm volatile("cp.async.commit_group;")
#define CPW0() asm volatile("cp.async.wait_group 0;")
#define CPW1() asm volatile("cp.async.wait_group 1;")
#define LDSM4(r0,r1,r2,r3,a) asm volatile("ldmatrix.sync.aligned.m8n8.x4.shared.b16 {%0,%1,%2,%3}, [%4];" \
    : "=r"(r0),"=r"(r1),"=r"(r2),"=r"(r3) : "r"(a))
#define LDSM4T(r0,r1,r2,r3,a) asm volatile("ldmatrix.sync.aligned.m8n8.x4.trans.shared.b16 {%0,%1,%2,%3}, [%4];" \
    : "=r"(r0),"=r"(r1),"=r"(r2),"=r"(r3) : "r"(a))
#define MMA16816(d0,d1,d2,d3, a0,a1,a2,a3, b0,b1) \
    asm volatile("mma.sync.aligned.m16n8k16.row.col.f32.bf16.bf16.f32 " \
        "{%0,%1,%2,%3}, {%4,%5,%6,%7}, {%8,%9}, {%0,%1,%2,%3};" \
        : "+f"(d0),"+f"(d1),"+f"(d2),"+f"(d3) \
        : "r"(a0),"r"(a1),"r"(a2),"r"(a3), "r"(b0),"r"(b1))

__device__ __forceinline__ unsigned pkbf2(float lo, float hi){
    unsigned d;
    asm("cvt.rn.bf16x2.f32 %0, %1, %2;" : "=r"(d) : "f"(hi), "f"(lo));
    return d;
}
#define EXP_B0 1064986316.0f
#define EXP_SA (12102203.161f * ATT_SCALE)
__device__ __forceinline__ float cexpb(float s, float base){
    float t = fmaf(s, EXP_SA, base);
    t = fmaxf(t, 0.f);
    return __int_as_float((int)t);
}

// ---------------- merged weight conversion ----------------
#define N0 (NLAY*768*256)
#define N1 (NLAY*256*256)
#define N2 (NLAY*NHID*256)
#define N3 (NLAY*256*NHID)
__global__ void conv4_kernel(const float* __restrict__ s0, const float* __restrict__ s1,
                             const float* __restrict__ s2, const float* __restrict__ s3)
{
    int i = (blockIdx.x*blockDim.x + threadIdx.x)*4;
    const float* s; __nv_bfloat16* d;
    if      (i < N0)         { s = s0 + i;              d = d_WqkvB + i; }
    else if (i < N0+N1)      { s = s1 + (i-N0);         d = d_WoB  + (i-N0); }
    else if (i < N0+N1+N2)   { s = s2 + (i-N0-N1);      d = d_W1B  + (i-N0-N1); }
    else                     { s = s3 + (i-N0-N1-N2);   d = d_W2B  + (i-N0-N1-N2); }
    float4 v = *(const float4*)s;
    uint2 o; o.x = pkbf2(v.x, v.y); o.y = pkbf2(v.z, v.w);
    *(uint2*)d = o;
}

// ---------------- rank-1 layer-0 QKV precompute ----------------
__global__ void prep0_kernel(const float* __restrict__ Wqkv, const float* __restrict__ bqkv,
                             const float* __restrict__ W_emb, const float* __restrict__ b_emb)
{
    int wid = threadIdx.x >> 5, lane = threadIdx.x & 31;
    for (int j = wid; j < 768; j += 8){
        const float* row = Wqkv + (size_t)j*256;
        float su = 0.f, sc = 0.f;
        #pragma unroll
        for (int i=0;i<8;i++){
            float w = row[lane + i*32];
            su = fmaf(w, W_emb[lane + i*32], su);
            sc = fmaf(w, b_emb[lane + i*32], sc);
        }
        #pragma unroll
        for (int o=16;o>0;o>>=1){
            su += __shfl_xor_sync(0xffffffffu, su, o);
            sc += __shfl_xor_sync(0xffffffffu, sc, o);
        }
        if (lane == 0){ d_u[j] = su; d_c[j] = sc + bqkv[j]; }
    }
}

// ---------------- embed + layer-0 QKV (rank-1) ----------------
__global__ void embed0_kernel(const float* __restrict__ inputs,
                              const float* __restrict__ W_emb,
                              const float* __restrict__ b_emb)
{
    int tok = blockIdx.x;
    int d   = threadIdx.x;
    float y = __ldg(&inputs[(size_t)tok*4]);
    float v = fmaf(y, W_emb[d], b_emb[d]);
    size_t gi = (size_t)tok*DMODEL + d;
    d_X32[gi] = v;
    d_Xb[gi]  = __float2bfloat16(v);
    #pragma unroll
    for (int t=0;t<3;t++){
        int j = d + t*256;
        float q = fmaf(y, d_u[j], d_c[j]);
        d_QKVb[(size_t)tok*768 + j] = __float2bfloat16(q);
    }
}

// ---------------- GEMM: C = A(MxK) * B(NxK)^T + bias [relu] -> bf16 ----------------
// tile 128x128, BK=64, cp.async double buffered (dynamic smem 73728B)
#define G_STG (128*72)          // elems per stage per matrix
__global__ __launch_bounds__(256) void gemm_kernel(
    const __nv_bfloat16* __restrict__ A,
    const __nv_bfloat16* __restrict__ B,
    const float* __restrict__ bias,
    __nv_bfloat16* __restrict__ outB,
    int N, int K, int relu, int mStride, int mOff)
{
    extern __shared__ __align__(16) unsigned char dynsm[];
    __nv_bfloat16* As = (__nv_bfloat16*)dynsm;       // [2][128*72]
    __nv_bfloat16* Bs = As + 2*G_STG;                // [2][128*72]
    float*         Cs = (float*)dynsm;               // 64*136 (epilogue alias)

    const int tid = threadIdx.x;
    const int wid = tid >> 5;
    const int wm  = wid >> 1, wn = wid & 1;
    const int m0  = (blockIdx.y * mStride + mOff) * 128;
    const int n0  = blockIdx.x * 128;

    wmma::fragment<wmma::accumulator,16,16,16,float> cf[2][4];
    #pragma unroll
    for (int i=0;i<2;i++)
        #pragma unroll
        for (int j=0;j<4;j++) wmma::fill_fragment(cf[i][j], 0.f);

    const int kIter = K >> 6;

    auto issue = [&](int i, int bf){
        const __nv_bfloat16* Ag = A + (size_t)m0*K + i*64;
        const __nv_bfloat16* Bg = B + (size_t)n0*K + i*64;
        __nv_bfloat16* Ad = As + bf*G_STG;
        __nv_bfloat16* Bd = Bs + bf*G_STG;
        #pragma unroll
        for (int c = tid; c < 1024; c += 256){
            int r = c >> 3, off = (c & 7)*8;
            CPA(smem_u32(&Ad[r*72+off]), Ag + (size_t)r*K + off);
            CPA(smem_u32(&Bd[r*72+off]), Bg + (size_t)r*K + off);
        }
    };

    issue(0, 0); CPC();
    for (int i = 0; i < kIter; i++){
        int buf = i & 1;
        if (i+1 < kIter){ issue(i+1, buf^1); CPC(); CPW1(); }
        else            { CPW0(); }
        __syncthreads();
        const __nv_bfloat16* Asb = As + buf*G_STG;
        const __nv_bfloat16* Bsb = Bs + buf*G_STG;
        #pragma unroll
        for (int kk = 0; kk < 64; kk += 16){
            wmma::fragment<wmma::matrix_a,16,16,16,__nv_bfloat16,wmma::row_major> af[2];
            wmma::fragment<wmma::matrix_b,16,16,16,__nv_bfloat16,wmma::col_major> bfr[4];
            #pragma unroll
            for (int x=0;x<2;x++) wmma::load_matrix_sync(af[x],  &Asb[(wm*32 + x*16)*72 + kk], 72);
            #pragma unroll
            for (int j=0;j<4;j++) wmma::load_matrix_sync(bfr[j], &Bsb[(wn*64 + j*16)*72 + kk], 72);
            #pragma unroll
            for (int x=0;x<2;x++)
                #pragma unroll
                for (int j=0;j<4;j++)
                    wmma::mma_sync(cf[x][j], af[x], bfr[j], cf[x][j]);
        }
        __syncthreads();
    }

    #pragma unroll
    for (int chunk = 0; chunk < 2; chunk++){
        if ((wm >> 1) == chunk){
            #pragma unroll
            for (int x=0;x<2;x++)
                #pragma unroll
                for (int j=0;j<4;j++)
                    wmma::store_matrix_sync(&Cs[((wm&1)*32 + x*16)*136 + wn*64 + j*16],
                                            cf[x][j], 136, wmma::mem_row_major);
        }
        __syncthreads();
        for (int e = tid; e < 64*128; e += 256){
            int cm = e >> 7, cn = e & 127;
            float v = Cs[cm*136+cn] + bias[n0+cn];
            if (relu) v = fmaxf(v, 0.f);
            outB[(size_t)(m0 + chunk*64 + cm)*N + n0 + cn] = __float2bfloat16(v);
        }
        __syncthreads();
    }
}

// ---------------- GEMM + bias + resid + LayerNorm fused epilogue ----------------
// tile 64x256, BK=32, BOTH A and B cp.async double buffered (dynamic smem 51200B)
#define GL_ASTG (64*40)
#define GL_BSTG (256*40)
__global__ __launch_bounds__(256) void gemm_ln_kernel(
    const __nv_bfloat16* __restrict__ A,
    const __nv_bfloat16* __restrict__ B,
    const float* __restrict__ bias,
    const float* __restrict__ g,
    const float* __restrict__ bta,
    int K, int sparse)
{
    extern __shared__ __align__(16) unsigned char dynsm[];
    __nv_bfloat16* As = (__nv_bfloat16*)dynsm;       // [2][64*40]
    __nv_bfloat16* Bs = As + 2*GL_ASTG;              // [2][256*40]
    float*         Cs = (float*)dynsm;               // [32][264] alias

    const int tid = threadIdx.x;
    const int wid = tid >> 5, lane = tid & 31;
    const int wm  = wid >> 2, wn = wid & 3;
    const int t64 = sparse ? ((blockIdx.y >> 1)*32 + 30 + (blockIdx.y & 1)) : blockIdx.y;
    const int m0  = t64 * 64;

    wmma::fragment<wmma::accumulator,16,16,16,float> cf[2][4];
    #pragma unroll
    for (int i=0;i<2;i++)
        #pragma unroll
        for (int j=0;j<4;j++) wmma::fill_fragment(cf[i][j], 0.f);

    const int kIter = K >> 5;

    auto issue = [&](int i, int bf){
        const __nv_bfloat16* Ag = A + (size_t)m0*K + i*32;
        const __nv_bfloat16* Bg = B + i*32;
        __nv_bfloat16* Ad = As + bf*GL_ASTG;
        __nv_bfloat16* Bd = Bs + bf*GL_BSTG;
        {
            int r = tid >> 2, off = (tid & 3)*8;
            CPA(smem_u32(&Ad[r*40+off]), Ag + (size_t)r*K + off);
        }
        #pragma unroll
        for (int c = tid; c < 1024; c += 256){
            int r = c >> 2, off = (c & 3)*8;
            CPA(smem_u32(&Bd[r*40+off]), Bg + (size_t)r*K + off);
        }
    };

    issue(0, 0); CPC();
    for (int i = 0; i < kIter; i++){
        int buf = i & 1;
        if (i+1 < kIter){ issue(i+1, buf^1); CPC(); CPW1(); }
        else            { CPW0(); }
        __syncthreads();
        const __nv_bfloat16* Asb = As + buf*GL_ASTG;
        const __nv_bfloat16* Bsb = Bs + buf*GL_BSTG;
        #pragma unroll
        for (int kk = 0; kk < 32; kk += 16){
            wmma::fragment<wmma::matrix_a,16,16,16,__nv_bfloat16,wmma::row_major> af[2];
            wmma::fragment<wmma::matrix_b,16,16,16,__nv_bfloat16,wmma::col_major> bfr[4];
            #pragma unroll
            for (int x=0;x<2;x++) wmma::load_matrix_sync(af[x],  &Asb[(wm*32 + x*16)*40 + kk], 40);
            #pragma unroll
            for (int j=0;j<4;j++) wmma::load_matrix_sync(bfr[j], &Bsb[(wn*64 + j*16)*40 + kk], 40);
            #pragma unroll
            for (int x=0;x<2;x++)
                #pragma unroll
                for (int j=0;j<4;j++)
                    wmma::mma_sync(cf[x][j], af[x], bfr[j], cf[x][j]);
        }
        __syncthreads();
    }

    #pragma unroll
    for (int chunk = 0; chunk < 2; chunk++){
        if (wm == chunk){
            #pragma unroll
            for (int x=0;x<2;x++)
                #pragma unroll
                for (int j=0;j<4;j++)
                    wmma::store_matrix_sync(&Cs[(x*16)*264 + wn*64 + j*16],
                                            cf[x][j], 264, wmma::mem_row_major);
        }
        __syncthreads();
        #pragma unroll
        for (int ii=0; ii<4; ii++){
            int rloc = wid*4 + ii;
            int tok  = m0 + chunk*32 + rloc;
            float v[8]; float s = 0.f;
            #pragma unroll
            for (int i=0;i<8;i++){
                int c = lane + i*32;
                v[i] = Cs[rloc*264 + c] + bias[c] + d_X32[(size_t)tok*DMODEL + c];
                s += v[i];
            }
            #pragma unroll
            for (int o=16;o>0;o>>=1) s += __shfl_xor_sync(0xffffffffu, s, o);
            float mean = s * (1.f/256.f);
            float q = 0.f;
            #pragma unroll
            for (int i=0;i<8;i++){ float dd = v[i]-mean; q = fmaf(dd, dd, q); }
            #pragma unroll
            for (int o=16;o>0;o>>=1) q += __shfl_xor_sync(0xffffffffu, q, o);
            float rstd = rsqrtf(q*(1.f/256.f) + 1e-5f);
            #pragma unroll
            for (int i=0;i<8;i++){
                int c = lane + i*32;
                float o = (v[i]-mean)*rstd*g[c] + bta[c];
                size_t gi = (size_t)tok*DMODEL + c;
                d_X32[gi] = o;
                d_Xb[gi]  = __float2bfloat16(o);
            }
        }
        __syncthreads();
    }
}

// ---------------- flash attention: 128 q rows, 128-row K/V tiles (two 64-col halves) ----------------
// qt = qtBase - blockIdx.x (heavy tiles first).  dynamic smem 51200B.
#define A_STG (128*40)
__global__ __launch_bounds__(256) void attn_kernel(int qtBase, int useMax)
{
    extern __shared__ __align__(16) unsigned char dynsm[];
    __nv_bfloat16* Qs = (__nv_bfloat16*)dynsm;       // 128*40
    __nv_bfloat16* Ks = Qs + A_STG;                  // [2][128*40]
    __nv_bfloat16* Vs = Ks + 2*A_STG;                // [2][128*40]

    const int tid = threadIdx.x, lane = tid & 31, w = tid >> 5;
    const int qt = qtBase - blockIdx.x;              // 128-row q tile (heavy first)
    const int bh = blockIdx.y, b = bh >> 3, h = bh & 7;
    const int g = lane >> 2, tig = lane & 3;
    const int r8 = lane & 7, sel = lane >> 3;
    const int rwBase = qt*128 + w*16;

    // prologue: Q + KV tile 0 (128 rows) via cp.async
    const __nv_bfloat16* Qg = d_QKVb + ((size_t)(b*SEQ + qt*128))*768 + h*32;
    const __nv_bfloat16* K0 = d_QKVb + ((size_t)(b*SEQ))*768 + 256 + h*32;
    #pragma unroll
    for (int c = tid; c < 512; c += 256){
        int r = c >> 2, off = (c & 3)*8;
        CPA(smem_u32(&Qs[r*40+off]), Qg + (size_t)r*768 + off);
        CPA(smem_u32(&Ks[r*40+off]), K0 + (size_t)r*768 + off);
        CPA(smem_u32(&Vs[r*40+off]), K0 + 256 + (size_t)r*768 + off);
    }
    CPC(); CPW0();
    __syncthreads();

    unsigned aq[2][4];
    {
        int row = w*16 + (sel & 1)*8 + r8;
        #pragma unroll
        for (int t=0;t<2;t++){
            unsigned addr = smem_u32(&Qs[row*40 + t*16 + (sel>>1)*8]);
            LDSM4(aq[t][0], aq[t][1], aq[t][2], aq[t][3], addr);
        }
    }

    float o[4][4];
    #pragma unroll
    for (int j=0;j<4;j++){ o[j][0]=0.f;o[j][1]=0.f;o[j][2]=0.f;o[j][3]=0.f; }
    float l0 = 0.f, l1 = 0.f;
    float m0v = -1e30f, m1v = -1e30f;
    const int gr0 = rwBase + g;

    for (int kt = 0; kt <= qt; kt++){
        int buf = kt & 1;
        if (kt < qt){
            int nb = buf ^ 1;
            const __nv_bfloat16* Kg = d_QKVb + ((size_t)(b*SEQ + (kt+1)*128))*768 + 256 + h*32;
            #pragma unroll
            for (int c = tid; c < 512; c += 256){
                int r = c >> 2, off = (c & 3)*8;
                CPA(smem_u32(&Ks[nb*A_STG + r*40+off]), Kg + (size_t)r*768 + off);
                CPA(smem_u32(&Vs[nb*A_STG + r*40+off]), Kg + 256 + (size_t)r*768 + off);
            }
            CPC(); CPW1();
        } else {
            CPW0();
        }
        __syncthreads();

        const __nv_bfloat16* Kb = Ks + buf*A_STG;
        const __nv_bfloat16* Vb = Vs + buf*A_STG;

        #pragma unroll
        for (int h2 = 0; h2 < 2; h2++){
            const int cb = kt*128 + h2*64;
            if (cb > rwBase + 15) break;     // fully masked for this warp

            // S = Q K^T (64 cols of this half)
            float s[8][4];
            #pragma unroll
            for (int j=0;j<8;j++){
                s[j][0]=0.f;s[j][1]=0.f;s[j][2]=0.f;s[j][3]=0.f;
                unsigned k0,k1,k2,k3;
                unsigned addr = smem_u32(&Kb[(h2*64 + j*8 + r8)*40 + sel*8]);
                LDSM4(k0,k1,k2,k3, addr);
                MMA16816(s[j][0],s[j][1],s[j][2],s[j][3],
                         aq[0][0],aq[0][1],aq[0][2],aq[0][3], k0,k1);
                MMA16816(s[j][0],s[j][1],s[j][2],s[j][3],
                         aq[1][0],aq[1][1],aq[1][2],aq[1][3], k2,k3);
            }

            if (cb + 63 > rwBase){
                #pragma unroll
                for (int j=0;j<8;j++){
                    int c0 = cb + j*8 + 2*tig;
                    if (c0   > gr0)   s[j][0] = -1e30f;
                    if (c0+1 > gr0)   s[j][1] = -1e30f;
                    if (c0   > gr0+8) s[j][2] = -1e30f;
                    if (c0+1 > gr0+8) s[j][3] = -1e30f;
                }
            }

            float base0 = EXP_B0, base1 = EXP_B0;
            if (useMax){
                float mt0 = -1e30f, mt1 = -1e30f;
                #pragma unroll
                for (int j=0;j<8;j++){
                    mt0 = fmaxf(mt0, fmaxf(s[j][0], s[j][1]));
                    mt1 = fmaxf(mt1, fmaxf(s[j][2], s[j][3]));
                }
                mt0 = fmaxf(mt0, __shfl_xor_sync(0xffffffffu, mt0, 1));
                mt0 = fmaxf(mt0, __shfl_xor_sync(0xffffffffu, mt0, 2));
                mt1 = fmaxf(mt1, __shfl_xor_sync(0xffffffffu, mt1, 1));
                mt1 = fmaxf(mt1, __shfl_xor_sync(0xffffffffu, mt1, 2));
                float nm0 = fmaxf(m0v, mt0), nm1 = fmaxf(m1v, mt1);
                base0 = EXP_B0 - EXP_SA*nm0;
                base1 = EXP_B0 - EXP_SA*nm1;
                float corr0 = cexpb(m0v, base0), corr1 = cexpb(m1v, base1);
                m0v = nm0; m1v = nm1;
                l0 *= corr0; l1 *= corr1;
                #pragma unroll
                for (int j=0;j<4;j++){
                    o[j][0] *= corr0; o[j][1] *= corr0;
                    o[j][2] *= corr1; o[j][3] *= corr1;
                }
            }

            unsigned pp[4][4];
            #pragma unroll
            for (int t=0;t<4;t++){
                float p00 = cexpb(s[2*t][0],   base0), p01 = cexpb(s[2*t][1],   base0);
                float p02 = cexpb(s[2*t][2],   base1), p03 = cexpb(s[2*t][3],   base1);
                float p10 = cexpb(s[2*t+1][0], base0), p11 = cexpb(s[2*t+1][1], base0);
                float p12 = cexpb(s[2*t+1][2], base1), p13 = cexpb(s[2*t+1][3], base1);
                l0 += p00 + p01 + p10 + p11;
                l1 += p02 + p03 + p12 + p13;
                pp[t][0] = pkbf2(p00, p01);
                pp[t][1] = pkbf2(p02, p03);
                pp[t][2] = pkbf2(p10, p11);
                pp[t][3] = pkbf2(p12, p13);
            }

            #pragma unroll
            for (int t=0;t<4;t++){
                unsigned v0,v1,v2,v3, x0,x1,x2,x3;
                int vrow = h2*64 + 16*t + (sel & 1)*8 + r8;
                unsigned addrA = smem_u32(&Vb[vrow*40 + (sel>>1)*8]);
                unsigned addrB = smem_u32(&Vb[vrow*40 + 16 + (sel>>1)*8]);
                LDSM4T(v0,v1,v2,v3, addrA);
                LDSM4T(x0,x1,x2,x3, addrB);
                MMA16816(o[0][0],o[0][1],o[0][2],o[0][3], pp[t][0],pp[t][1],pp[t][2],pp[t][3], v0,v1);
                MMA16816(o[1][0],o[1][1],o[1][2],o[1][3], pp[t][0],pp[t][1],pp[t][2],pp[t][3], v2,v3);
                MMA16816(o[2][0],o[2][1],o[2][2],o[2][3], pp[t][0],pp[t][1],pp[t][2],pp[t][3], x0,x1);
                MMA16816(o[3][0],o[3][1],o[3][2],o[3][3], pp[t][0],pp[t][1],pp[t][2],pp[t][3], x2,x3);
            }
        }
        __syncthreads();
    }

    l0 += __shfl_xor_sync(0xffffffffu, l0, 1);
    l0 += __shfl_xor_sync(0xffffffffu, l0, 2);
    l1 += __shfl_xor_sync(0xffffffffu, l1, 1);
    l1 += __shfl_xor_sync(0xffffffffu, l1, 2);
    float rl0 = __fdividef(1.f, l0), rl1 = __fdividef(1.f, l1);
    __nv_bfloat16* Og0 = d_ATTb + ((size_t)(b*SEQ + rwBase + g))*256 + h*32;
    __nv_bfloat16* Og1 = Og0 + (size_t)8*256;
    #pragma unroll
    for (int j=0;j<4;j++){
        int dcol = j*8 + 2*tig;
        *(unsigned*)&Og0[dcol] = pkbf2(o[j][0]*rl0, o[j][1]*rl0);
        *(unsigned*)&Og1[dcol] = pkbf2(o[j][2]*rl1, o[j][3]*rl1);
    }
}

// ---------------- dec + hist + IDM + fusion ----------------
__global__ void final_kernel(const float* __restrict__ inputs,
    const float* __restrict__ his,
    const float* __restrict__ W_dec, const float* __restrict__ b_dec,
    const float* __restrict__ W_fus, const float* __restrict__ b_fus,
    float* __restrict__ out)
{
    __shared__ float dec[8], yidm[8][LOUT], lastpos[8], dvb[8];
    int tid = threadIdx.x, wid = tid>>5, lane = tid&31;
    {
        const float* row = d_X32 + ((size_t)(wid*SEQ + SEQ-1))*DMODEL;
        float s = 0.f;
        #pragma unroll
        for (int i=0;i<8;i++){ int d_ = lane + i*32; s += row[d_]*W_dec[d_]; }
        #pragma unroll
        for (int o=16;o>0;o>>=1) s += __shfl_xor_sync(0xffffffffu, s, o);
        if (lane==0) dec[wid] = s + b_dec[0];
    }
    if (tid < 8){
        int b = tid;
        float lp = inputs[((size_t)(b*SEQ + SEQ-1))*4];
        lastpos[b] = lp;
        dvb[b] = (lp - inputs[((size_t)(b*SEQ + SEQ-1-LOUT))*4]) / 50.f;
    }
    __syncthreads();

    if (tid < 8){
        int b = tid;
        const float* il = inputs + ((size_t)(b*SEQ + SEQ-1))*4;
        float y = il[0], v = il[1], sg = il[2], dv = il[3];
        const float sqab2 = 2.449489742783178f;
        float sx = 2.0f + fmaxf(0.f, v*1.5f + v*dv/sqab2);
        float t = v/30.0f; float p = t*t; p *= p;
        float rr = sx/sg;
        float af = (1.f - p - rr*rr);
        float v0 = fmaxf(v + af*0.1f, 0.f);
        float v0last = __shfl_sync(0xffu, v0, 7);   // reference's v0[-1] broadcast
        float yp = y + v0last*0.1f;
        float vp = v0;
        yidm[b][0] = yp;
        for (int j=0;j<LOUT-1;j++){
            float hp = his[((size_t)(b*LOUT + j))*2];
            float hv = his[((size_t)(b*LOUT + j))*2 + 1];
            float dvj = hv - vp;
            float sj  = hp - yp;
            float sxj = 2.0f + fmaxf(0.f, vp*1.5f + vp*dvj/sqab2);
            float tt = vp/30.0f; float q4 = tt*tt; q4 *= q4;
            float r2 = sxj/sj;
            float acc = (1.f - q4 - r2*r2);
            float v2 = vp + acc*0.1f;
            v2 = (v2 <= 0.f) ? 0.f : v2;
            yp = yp + v2*0.1f;
            yidm[b][j+1] = yp;
            vp = v2;
        }
    }
    __syncthreads();

    float w0 = W_fus[0], w1 = W_fus[1], w2 = W_fus[2], bb = b_fus[0];
    for (int t = tid; t < BATCH*LOUT; t += 256){
        int b = t / LOUT, l = t % LOUT;
        out[t] = w0*dec[b] + w1*(lastpos[b] + dvb[b]*(float)(l+1)) + w2*yidm[b][l] + bb;
    }
}

// ---------------- launcher ----------------
#define GEMM_SMEM   73728
#define GLN_SMEM    51200
#define ATT_SMEM    51200

extern "C" void kernel_launch(void* const* d_in, const int* in_sizes, int n_in,
                              void* d_out, int out_size)
{
    (void)in_sizes; (void)n_in; (void)out_size;
    const float* inputs = (const float*)d_in[0];
    const float* his    = (const float*)d_in[1];
    const float* W_emb  = (const float*)d_in[2];
    const float* b_emb  = (const float*)d_in[3];
    const float* Wqkv   = (const float*)d_in[4];
    const float* bqkv   = (const float*)d_in[5];
    const float* Wo     = (const float*)d_in[6];
    const float* bo     = (const float*)d_in[7];
    const float* W1     = (const float*)d_in[8];
    const float* b1     = (const float*)d_in[9];
    const float* W2     = (const float*)d_in[10];
    const float* b2     = (const float*)d_in[11];
    const float* ln1g   = (const float*)d_in[12];
    const float* ln1b   = (const float*)d_in[13];
    const float* ln2g   = (const float*)d_in[14];
    const float* ln2b   = (const float*)d_in[15];
    const float* W_dec  = (const float*)d_in[16];
    const float* b_dec  = (const float*)d_in[17];
    const float* W_fus  = (const float*)d_in[18];
    const float* b_fus  = (const float*)d_in[19];
    float* out = (float*)d_out;

    cudaFuncSetAttribute(gemm_kernel,    cudaFuncAttributeMaxDynamicSharedMemorySize, GEMM_SMEM);
    cudaFuncSetAttribute(gemm_ln_kernel, cudaFuncAttributeMaxDynamicSharedMemorySize, GLN_SMEM);
    cudaFuncSetAttribute(attn_kernel,    cudaFuncAttributeMaxDynamicSharedMemorySize, ATT_SMEM);

    void *pXb_, *pHb_, *pWq_, *pWo_, *pW1_, *pW2_, *pATT_, *pQKV_;
    cudaGetSymbolAddress(&pXb_,  d_Xb);
    cudaGetSymbolAddress(&pHb_,  d_Hb);
    cudaGetSymbolAddress(&pWq_,  d_WqkvB);
    cudaGetSymbolAddress(&pWo_,  d_WoB);
    cudaGetSymbolAddress(&pW1_,  d_W1B);
    cudaGetSymbolAddress(&pW2_,  d_W2B);
    cudaGetSymbolAddress(&pATT_, d_ATTb);
    cudaGetSymbolAddress(&pQKV_, d_QKVb);

    __nv_bfloat16* Xb   = (__nv_bfloat16*)pXb_;
    __nv_bfloat16* Hb   = (__nv_bfloat16*)pHb_;
    __nv_bfloat16* WqB  = (__nv_bfloat16*)pWq_;
    __nv_bfloat16* WoB  = (__nv_bfloat16*)pWo_;
    __nv_bfloat16* W1B  = (__nv_bfloat16*)pW1_;
    __nv_bfloat16* W2B  = (__nv_bfloat16*)pW2_;
    __nv_bfloat16* ATTb = (__nv_bfloat16*)pATT_;
    __nv_bfloat16* QKVb = (__nv_bfloat16*)pQKV_;

    conv4_kernel<<<(N0+N1+N2+N3)/4/256, 256>>>(Wqkv, Wo, W1, W2);
    prep0_kernel<<<1, 256>>>(Wqkv, bqkv, W_emb, b_emb);
    embed0_kernel<<<NTOK, 256>>>(inputs, W_emb, b_emb);

    for (int l = 0; l < NLAY; l++){
        int sp = (l == NLAY-1);
        int useMax = (l == 0);

        if (l > 0)
            gemm_kernel<<<dim3(6,128), 256, GEMM_SMEM>>>(Xb, WqB + (size_t)l*768*256,
                bqkv + l*768, QKVb, 768, 256, 0, 1, 0);

        if (!sp) attn_kernel<<<dim3(16,64), 256, ATT_SMEM>>>(15, useMax);
        else     attn_kernel<<<dim3(1,64),  256, ATT_SMEM>>>(15, useMax);

        gemm_ln_kernel<<<dim3(1, sp?16:256), 256, GLN_SMEM>>>(ATTb, WoB + (size_t)l*256*256,
            bo + l*256, ln1g + l*256, ln1b + l*256, 256, sp);

        gemm_kernel<<<dim3(8, sp?8:128), 256, GEMM_SMEM>>>(Xb, W1B + (size_t)l*1024*256,
            b1 + l*1024, Hb, 1024, 256, 1, sp?16:1, sp?15:0);

        gemm_ln_kernel<<<dim3(1, sp?16:256), 256, GLN_SMEM>>>(Hb, W2B + (size_t)l*256*1024,
            b2 + l*256, ln2g + l*256, ln2b + l*256, 1024, sp);
    }

    final_kernel<<<1, 256>>>(inputs, his, W_dec, b_dec, W_fus, b_fus, out);
}